// round 5
// baseline (speedup 1.0000x reference)
#include <cuda_runtime.h>
#include <cfloat>
#include <cstddef>

#define NB 64   // batch

// ---------------- scratch buffers (device globals; no allocations) ----------
__device__ __align__(16) float g_A1[(size_t)NB*64*64*64];   // enc conv1 out  [B,64,64,64]
__device__ __align__(16) float g_A2[(size_t)NB*128*32*32];  // enc conv2 out  [B,128,32,32]
__device__ __align__(16) float g_A3[(size_t)NB*128*32*32];  // enc conv3/res  [B,128,32,32]
__device__ __align__(16) float g_T [(size_t)NB*32*32*32];   // res 3x3 temp   [B,32,32,32]
__device__ __align__(16) float g_Z [(size_t)NB*32*32*64];   // z NHWC         [B,32,32,64]
__device__ __align__(16) float g_ZQ[(size_t)NB*64*32*32];   // z_q NCHW       [B,64,32,32]
__device__ __align__(16) float g_D1[(size_t)NB*128*32*32];  // dec trunk      [B,128,32,32]
__device__ __align__(16) float g_U1[(size_t)NB*64*64*64];   // dec upsample   [B,64,64,64]
__device__ __align__(16) float g_W1T[128*64*9];             // flipped dw1 as conv weight
__device__ float  g_ESQ[1024];
__device__ int    g_IDX[65536];
__device__ double g_PART[512];

// id -> buffer resolution done on DEVICE (avoids any host symbol-address API)
__device__ __forceinline__ const float* gbuf_c(int id, const float* ext){
  switch(id){
    case 0: return g_A1; case 1: return g_A2; case 2: return g_A3;
    case 3: return g_T;  case 4: return g_Z;  case 5: return g_ZQ;
    case 6: return g_D1; case 7: return g_U1; case 8: return g_W1T;
    default: return ext;
  }
}
__device__ __forceinline__ float* gbuf(int id){
  switch(id){
    case 0: return g_A1; case 1: return g_A2; case 2: return g_A3;
    case 3: return g_T;  case 4: return g_Z;  case 5: return g_ZQ;
    case 6: return g_D1; default: return g_U1;
  }
}

// ---------------- 4x4 stride-2 pad-1 conv, fused ReLU out --------------------
// thread: 4 couts x 4 x-pixels. weights via float4.
template<int CIN, int COUT, int HIN>
__global__ void k_conv4s2(const float* __restrict__ ext_in, int in_id,
                          const float* __restrict__ w,
                          const float* __restrict__ bias, int out_id)
{
  constexpr int HOUT = HIN/2;
  const float* in = gbuf_c(in_id, ext_in);
  float* out = gbuf(out_id);
  int cog = blockIdx.z % (COUT/4);
  int b   = blockIdx.z / (COUT/4);
  int co0 = cog*4;
  int x0  = threadIdx.x*4;
  int y   = blockIdx.y*blockDim.y + threadIdx.y;
  float acc[4][4];
  #pragma unroll
  for (int j=0;j<4;j++){ float bv=__ldg(bias+co0+j);
    #pragma unroll
    for (int p=0;p<4;p++) acc[j][p]=bv; }
  for (int ci=0; ci<CIN; ci++){
    const float* ip = in + ((size_t)(b*CIN+ci))*HIN*HIN;
    #pragma unroll
    for (int ky=0;ky<4;ky++){
      int iy = 2*y+ky-1;
      if (iy<0 || iy>=HIN) continue;
      const float* row = ip + (size_t)iy*HIN;
      float v[10];
      int xb = 2*x0-1;
      #pragma unroll
      for (int t=0;t<10;t++){ int ix=xb+t; v[t]=(ix>=0&&ix<HIN)?__ldg(row+ix):0.f; }
      #pragma unroll
      for (int j=0;j<4;j++){
        float4 wv = *reinterpret_cast<const float4*>(w + ((size_t)((co0+j)*CIN+ci)*4+ky)*4);
        #pragma unroll
        for (int p=0;p<4;p++)
          acc[j][p] = fmaf(wv.x,v[2*p],fmaf(wv.y,v[2*p+1],
                      fmaf(wv.z,v[2*p+2],fmaf(wv.w,v[2*p+3],acc[j][p]))));
      }
    }
  }
  #pragma unroll
  for (int j=0;j<4;j++){
    float* op = out + (((size_t)(b*COUT+co0+j))*HOUT + y)*HOUT + x0;
    #pragma unroll
    for (int p=0;p<4;p++) op[p] = fmaxf(acc[j][p],0.f);
  }
}

// ---------------- 3x3 stride-1 pad-1 conv at 32x32 ---------------------------
// thread: COT couts x 4 x-pixels. RIN = relu input, ROUT = relu output.
template<int CIN,int COUT,int COT,bool RIN,bool ROUT,bool HASB>
__global__ void k_conv3(int in_id, const float* __restrict__ wext, int w_id,
                        const float* __restrict__ bias, int out_id)
{
  const float* in = gbuf_c(in_id, nullptr);
  const float* w  = gbuf_c(w_id, wext);
  float* out = gbuf(out_id);
  int cog = blockIdx.z % (COUT/COT);
  int b   = blockIdx.z / (COUT/COT);
  int co0 = cog*COT;
  int x0 = threadIdx.x*4;
  int y  = blockIdx.y*16 + threadIdx.y;
  float acc[COT][4];
  #pragma unroll
  for (int j=0;j<COT;j++){ float bv = HASB?__ldg(bias+co0+j):0.f;
    #pragma unroll
    for (int p=0;p<4;p++) acc[j][p]=bv; }
  for (int ci=0;ci<CIN;ci++){
    const float* ip = in + (size_t)(b*CIN+ci)*1024;
    #pragma unroll
    for (int ky=0;ky<3;ky++){
      int iy=y+ky-1;
      if (iy<0||iy>=32) continue;
      const float* row = ip + iy*32;
      float v[6];
      #pragma unroll
      for (int t=0;t<6;t++){
        int ix=x0-1+t;
        float u=(ix>=0&&ix<32)?__ldg(row+ix):0.f;
        v[t]=RIN?fmaxf(u,0.f):u;
      }
      #pragma unroll
      for (int j=0;j<COT;j++){
        const float* wp = w + ((size_t)(co0+j)*CIN+ci)*9 + ky*3;
        float w0=__ldg(wp), w1=__ldg(wp+1), w2=__ldg(wp+2);
        #pragma unroll
        for (int p=0;p<4;p++)
          acc[j][p]=fmaf(w0,v[p],fmaf(w1,v[p+1],fmaf(w2,v[p+2],acc[j][p])));
      }
    }
  }
  #pragma unroll
  for (int j=0;j<COT;j++){
    float* op = out + ((size_t)(b*COUT+co0+j)*32 + y)*32 + x0;
    #pragma unroll
    for (int p=0;p<4;p++) op[p] = ROUT?fmaxf(acc[j][p],0.f):acc[j][p];
  }
}

// ---------------- 1x1 conv, residual-add into x ------------------------------
template<int CIN,int COUT>
__global__ void k_res1x1(int t_id, const float* __restrict__ w, int x_id)
{
  const float* t = gbuf_c(t_id, nullptr);
  float* x = gbuf(x_id);
  int co0 = blockIdx.x*4;
  int b = blockIdx.y;
  int p0 = threadIdx.x*8;
  float acc[4][8];
  #pragma unroll
  for (int j=0;j<4;j++)
    #pragma unroll
    for (int u=0;u<8;u++) acc[j][u]=0.f;
  for (int ci=0;ci<CIN;ci++){
    const float* ip = t + (size_t)(b*CIN+ci)*1024 + p0;
    float4 va = *reinterpret_cast<const float4*>(ip);
    float4 vb = *reinterpret_cast<const float4*>(ip+4);
    #pragma unroll
    for (int j=0;j<4;j++){
      float wv = __ldg(w + (size_t)(co0+j)*CIN + ci);
      acc[j][0]=fmaf(wv,va.x,acc[j][0]); acc[j][1]=fmaf(wv,va.y,acc[j][1]);
      acc[j][2]=fmaf(wv,va.z,acc[j][2]); acc[j][3]=fmaf(wv,va.w,acc[j][3]);
      acc[j][4]=fmaf(wv,vb.x,acc[j][4]); acc[j][5]=fmaf(wv,vb.y,acc[j][5]);
      acc[j][6]=fmaf(wv,vb.z,acc[j][6]); acc[j][7]=fmaf(wv,vb.w,acc[j][7]);
    }
  }
  #pragma unroll
  for (int j=0;j<4;j++){
    float* op = x + (size_t)(b*COUT+co0+j)*1024 + p0;
    #pragma unroll
    for (int u=0;u<8;u++) op[u] += acc[j][u];
  }
}

// ---------------- pre-quant 1x1: relu(in) -> z (NHWC) ------------------------
__global__ void k_pq(int in_id, const float* __restrict__ w,
                     const float* __restrict__ bias)
{
  const float* h = gbuf_c(in_id, nullptr);
  int d0 = blockIdx.x*4;
  int b = blockIdx.y;
  int p0 = threadIdx.x*8;
  float acc[4][8];
  #pragma unroll
  for (int j=0;j<4;j++){ float bv=__ldg(bias+d0+j);
    #pragma unroll
    for (int u=0;u<8;u++) acc[j][u]=bv; }
  for (int ci=0;ci<128;ci++){
    const float* ip = h + (size_t)(b*128+ci)*1024 + p0;
    float4 va = *reinterpret_cast<const float4*>(ip);
    float4 vb = *reinterpret_cast<const float4*>(ip+4);
    va.x=fmaxf(va.x,0.f); va.y=fmaxf(va.y,0.f); va.z=fmaxf(va.z,0.f); va.w=fmaxf(va.w,0.f);
    vb.x=fmaxf(vb.x,0.f); vb.y=fmaxf(vb.y,0.f); vb.z=fmaxf(vb.z,0.f); vb.w=fmaxf(vb.w,0.f);
    #pragma unroll
    for (int j=0;j<4;j++){
      float wv = __ldg(w + (size_t)(d0+j)*128 + ci);
      acc[j][0]=fmaf(wv,va.x,acc[j][0]); acc[j][1]=fmaf(wv,va.y,acc[j][1]);
      acc[j][2]=fmaf(wv,va.z,acc[j][2]); acc[j][3]=fmaf(wv,va.w,acc[j][3]);
      acc[j][4]=fmaf(wv,vb.x,acc[j][4]); acc[j][5]=fmaf(wv,vb.y,acc[j][5]);
      acc[j][6]=fmaf(wv,vb.z,acc[j][6]); acc[j][7]=fmaf(wv,vb.w,acc[j][7]);
    }
  }
  #pragma unroll
  for (int p=0;p<8;p++){
    float4 o = make_float4(acc[0][p],acc[1][p],acc[2][p],acc[3][p]);
    *reinterpret_cast<float4*>(g_Z + (size_t)(b*1024+p0+p)*64 + d0) = o;
  }
}

// ---------------- codebook squared norms -------------------------------------
__global__ void k_esq(const float* __restrict__ emb){
  int k = blockIdx.x*blockDim.x + threadIdx.x;
  if (k >= 1024) return;
  const float4* e = reinterpret_cast<const float4*>(emb + (size_t)k*64);
  float s = 0.f;
  #pragma unroll
  for (int i=0;i<16;i++){
    float4 v = e[i];
    s = fmaf(v.x,v.x,fmaf(v.y,v.y,fmaf(v.z,v.z,fmaf(v.w,v.w,s))));
  }
  g_ESQ[k] = s;
}

// ---------------- VQ: argmin, gather to NCHW, loss partials ------------------
__global__ void k_vq(const float* __restrict__ emb){
  __shared__ __align__(16) float sE[128*64];
  __shared__ float sQ[128];
  __shared__ double sred[128];
  int tid = threadIdx.x;
  int n = blockIdx.x*128 + tid;
  int b = n >> 10, p = n & 1023;
  float zr[64];
  {
    const float4* zp = reinterpret_cast<const float4*>(g_Z + (size_t)n*64);
    float4* zr4 = reinterpret_cast<float4*>(zr);
    #pragma unroll
    for (int i=0;i<16;i++) zr4[i] = zp[i];
  }
  float best = FLT_MAX; int bi = 0;
  for (int c=0;c<8;c++){
    const float4* src = reinterpret_cast<const float4*>(emb) + (size_t)c*2048;
    float4* dst = reinterpret_cast<float4*>(sE);
    #pragma unroll
    for (int r=0;r<16;r++) dst[tid + r*128] = src[tid + r*128];
    sQ[tid] = g_ESQ[c*128+tid];
    __syncthreads();
    for (int kk=0;kk<128;kk++){
      const float4* e = reinterpret_cast<const float4*>(sE + kk*64);
      float d0=0.f,d1=0.f,d2=0.f,d3=0.f;
      #pragma unroll
      for (int i=0;i<16;i++){
        float4 ev = e[i];
        float4 zv = reinterpret_cast<float4*>(zr)[i];
        d0 = fmaf(ev.x,zv.x,d0); d1 = fmaf(ev.y,zv.y,d1);
        d2 = fmaf(ev.z,zv.z,d2); d3 = fmaf(ev.w,zv.w,d3);
      }
      float sc = sQ[kk] - 2.f*((d0+d1)+(d2+d3));
      if (sc < best){ best = sc; bi = c*128+kk; }   // strict < : first min (jnp.argmin)
    }
    __syncthreads();
  }
  g_IDX[n] = bi;
  const float* er = emb + (size_t)bi*64;
  float ls = 0.f;
  #pragma unroll
  for (int d=0; d<64; d++){
    float e = __ldg(er+d);
    g_ZQ[(size_t)(b*64+d)*1024 + p] = e;
    float df = e - zr[d];
    ls = fmaf(df,df,ls);
  }
  sred[tid] = (double)ls;
  __syncthreads();
  #pragma unroll
  for (int s=64;s>0;s>>=1){
    if (tid<s) sred[tid] += sred[tid+s];
    __syncthreads();
  }
  if (tid==0) g_PART[blockIdx.x] = sred[0];
}

// ---------------- flip/transpose dw1 (I,O,3,3) -> conv weight (O,I,3,3) ------
__global__ void k_wt(const float* __restrict__ dw1){
  int t = blockIdx.x*blockDim.x + threadIdx.x;
  if (t >= 128*64*9) return;
  int kx = t%3, ky=(t/3)%3, ci=(t/9)%64, co=t/(9*64);
  g_W1T[t] = dw1[(size_t)(ci*128+co)*9 + (2-ky)*3 + (2-kx)];
}

// ---------------- ConvTranspose 4x4 s2 p1: 128ch@32 -> 64ch@64, relu in+out --
__global__ void k_convT2(const float* __restrict__ w, const float* __restrict__ bias)
{
  const float* in = g_D1;
  float* out = g_U1;
  int co0 = blockIdx.x*4;
  int b   = blockIdx.z;
  int xq  = threadIdx.x;
  int yq  = blockIdx.y*8 + threadIdx.y;
  float acc[4][4];
  #pragma unroll
  for (int j=0;j<4;j++)
    #pragma unroll
    for (int q=0;q<4;q++) acc[j][q]=0.f;
  for (int ci=0;ci<128;ci++){
    const float* ip = in + (size_t)(b*128+ci)*1024;
    float r[3][3];
    #pragma unroll
    for (int dy=0;dy<3;dy++){
      int iy = yq+dy-1;
      #pragma unroll
      for (int dx=0;dx<3;dx++){
        int ix = xq+dx-1;
        r[dy][dx] = (iy>=0&&iy<32&&ix>=0&&ix<32)?fmaxf(__ldg(ip+iy*32+ix),0.f):0.f;
      }
    }
    const float4* wb4 = reinterpret_cast<const float4*>(w + ((size_t)ci*64 + co0)*16);
    #pragma unroll
    for (int j=0;j<4;j++){
      float4 w0=wb4[j*4+0], w1=wb4[j*4+1], w2=wb4[j*4+2], w3=wb4[j*4+3];
      acc[j][0] += w1.y*r[1][1] + w1.w*r[1][0] + w3.y*r[0][1] + w3.w*r[0][0]; // (oy even, ox even)
      acc[j][1] += w1.x*r[1][2] + w1.z*r[1][1] + w3.x*r[0][2] + w3.z*r[0][1]; // (even, odd)
      acc[j][2] += w0.y*r[2][1] + w0.w*r[2][0] + w2.y*r[1][1] + w2.w*r[1][0]; // (odd, even)
      acc[j][3] += w0.x*r[2][2] + w0.z*r[2][1] + w2.x*r[1][2] + w2.z*r[1][1]; // (odd, odd)
    }
  }
  #pragma unroll
  for (int j=0;j<4;j++){
    float bv = __ldg(bias+co0+j);
    #pragma unroll
    for (int py=0;py<2;py++)
      #pragma unroll
      for (int px=0;px<2;px++){
        int oy=2*yq+py, ox=2*xq+px;
        out[((size_t)(b*64+co0+j)*64+oy)*64+ox] = fmaxf(acc[j][py*2+px]+bv,0.f);
      }
  }
}

// ---------------- ConvTranspose 4x4 s2 p1: 64ch@64 -> 3ch@128 (recon) --------
__global__ void k_convT3(const float* __restrict__ w, const float* __restrict__ bias,
                         float* __restrict__ out)
{
  const float* in = g_U1;
  int b  = blockIdx.z;
  int xq = blockIdx.x*32 + threadIdx.x;   // 0..63
  int yq = blockIdx.y*8  + threadIdx.y;   // 0..63
  float acc[3][4];
  #pragma unroll
  for (int j=0;j<3;j++)
    #pragma unroll
    for (int q=0;q<4;q++) acc[j][q]=0.f;
  for (int ci=0;ci<64;ci++){
    const float* ip = in + (size_t)(b*64+ci)*4096;
    float r[3][3];
    #pragma unroll
    for (int dy=0;dy<3;dy++){
      int iy = yq+dy-1;
      #pragma unroll
      for (int dx=0;dx<3;dx++){
        int ix = xq+dx-1;
        r[dy][dx] = (iy>=0&&iy<64&&ix>=0&&ix<64)?__ldg(ip+iy*64+ix):0.f;
      }
    }
    const float4* wb4 = reinterpret_cast<const float4*>(w + (size_t)ci*48);
    #pragma unroll
    for (int j=0;j<3;j++){
      float4 w0=wb4[j*4+0], w1=wb4[j*4+1], w2=wb4[j*4+2], w3=wb4[j*4+3];
      acc[j][0] += w1.y*r[1][1] + w1.w*r[1][0] + w3.y*r[0][1] + w3.w*r[0][0];
      acc[j][1] += w1.x*r[1][2] + w1.z*r[1][1] + w3.x*r[0][2] + w3.z*r[0][1];
      acc[j][2] += w0.y*r[2][1] + w0.w*r[2][0] + w2.y*r[1][1] + w2.w*r[1][0];
      acc[j][3] += w0.x*r[2][2] + w0.z*r[2][1] + w2.x*r[1][2] + w2.z*r[1][1];
    }
  }
  #pragma unroll
  for (int j=0;j<3;j++){
    float bv = __ldg(bias+j);
    #pragma unroll
    for (int py=0;py<2;py++)
      #pragma unroll
      for (int px=0;px<2;px++){
        int oy=2*yq+py, ox=2*xq+px;
        out[((size_t)(b*3+j)*128+oy)*128+ox] = acc[j][py*2+px] + bv;
      }
  }
}

// ---------------- finalize: idx as float + deterministic loss ----------------
__global__ void k_final(float* __restrict__ out){
  int t = blockIdx.x*blockDim.x + threadIdx.x;
  if (t < 65536) out[3145730 + t] = (float)g_IDX[t];
  if (t == 0){
    double s = 0.0;
    for (int i=0;i<512;i++) s += g_PART[i];
    float m = (float)(s / 4194304.0);
    out[3145728] = m;   // codebook_loss
    out[3145729] = m;   // commitment_loss (identical value)
  }
}

// ---------------- launcher ---------------------------------------------------
extern "C" void kernel_launch(void* const* d_in, const int* in_sizes, int n_in,
                              void* d_out, int out_size)
{
  const float* patch=(const float*)d_in[0];
  const float* ew1=(const float*)d_in[1];  const float* eb1=(const float*)d_in[2];
  const float* ew2=(const float*)d_in[3];  const float* eb2=(const float*)d_in[4];
  const float* ew3=(const float*)d_in[5];  const float* eb3=(const float*)d_in[6];
  const float* er1a=(const float*)d_in[7]; const float* er1b=(const float*)d_in[8];
  const float* er2a=(const float*)d_in[9]; const float* er2b=(const float*)d_in[10];
  const float* pqw=(const float*)d_in[11]; const float* pqb=(const float*)d_in[12];
  const float* emb=(const float*)d_in[13];
  const float* dw1=(const float*)d_in[14]; const float* db1=(const float*)d_in[15];
  const float* dr1a=(const float*)d_in[16];const float* dr1b=(const float*)d_in[17];
  const float* dr2a=(const float*)d_in[18];const float* dr2b=(const float*)d_in[19];
  const float* dw2=(const float*)d_in[20]; const float* db2=(const float*)d_in[21];
  const float* dw3=(const float*)d_in[22]; const float* db3=(const float*)d_in[23];
  float* out = (float*)d_out;
  (void)in_sizes; (void)n_in; (void)out_size;

  // codebook norms + decoder stride-1 weight transform (cheap, every launch)
  k_esq<<<4,256>>>(emb);
  k_wt<<<288,256>>>(dw1);

  // encoder
  k_conv4s2<3,64,128> <<<dim3(1,4,1024), dim3(16,16)>>>(patch, -1, ew1, eb1, 0);
  k_conv4s2<64,128,64><<<dim3(1,1,2048), dim3(8,32)>>>(nullptr, 0, ew2, eb2, 1);
  k_conv3<128,128,8,false,false,true><<<dim3(1,2,1024), dim3(8,16)>>>(1, ew3, -1, eb3, 2);
  // residual block 1
  k_conv3<128,32,4,true,true,false><<<dim3(1,2,512), dim3(8,16)>>>(2, er1a, -1, nullptr, 3);
  k_res1x1<32,128><<<dim3(32,NB),128>>>(3, er1b, 2);
  // residual block 2
  k_conv3<128,32,4,true,true,false><<<dim3(1,2,512), dim3(8,16)>>>(2, er2a, -1, nullptr, 3);
  k_res1x1<32,128><<<dim3(32,NB),128>>>(3, er2b, 2);
  // pre-quant (relu fused into input)
  k_pq<<<dim3(16,NB),128>>>(2, pqw, pqb);
  // vector quantization
  k_vq<<<512,128>>>(emb);

  // decoder
  k_conv3<64,128,8,false,false,true><<<dim3(1,2,1024), dim3(8,16)>>>(5, nullptr, 8, db1, 6);
  k_conv3<128,32,4,true,true,false><<<dim3(1,2,512), dim3(8,16)>>>(6, dr1a, -1, nullptr, 3);
  k_res1x1<32,128><<<dim3(32,NB),128>>>(3, dr1b, 6);
  k_conv3<128,32,4,true,true,false><<<dim3(1,2,512), dim3(8,16)>>>(6, dr2a, -1, nullptr, 3);
  k_res1x1<32,128><<<dim3(32,NB),128>>>(3, dr2b, 6);
  k_convT2<<<dim3(16,4,NB), dim3(32,8)>>>(dw2, db2);
  k_convT3<<<dim3(2,8,NB),  dim3(32,8)>>>(dw3, db3, out);

  // losses + indices
  k_final<<<256,256>>>(out);
}

// round 7
// speedup vs baseline: 1.1114x; 1.1114x over previous
#include <cuda_runtime.h>
#include <cfloat>
#include <cstddef>

#define NB 64   // batch

// ---------------- scratch buffers (device globals; no allocations) ----------
__device__ __align__(16) float g_A1[(size_t)NB*64*64*64];   // enc conv1 out  [B,64,64,64]
__device__ __align__(16) float g_A2[(size_t)NB*128*32*32];  // enc conv2 out  [B,128,32,32]
__device__ __align__(16) float g_A3[(size_t)NB*128*32*32];  // enc conv3/res  [B,128,32,32]
__device__ __align__(16) float g_T [(size_t)NB*32*32*32];   // res 3x3 temp   [B,32,32,32]
__device__ __align__(16) float g_Z [(size_t)NB*32*32*64];   // z NHWC         [B,32,32,64]
__device__ __align__(16) float g_ZQ[(size_t)NB*64*32*32];   // z_q NCHW       [B,64,32,32]
__device__ __align__(16) float g_D1[(size_t)NB*128*32*32];  // dec trunk      [B,128,32,32]
__device__ __align__(16) float g_U1[(size_t)NB*64*64*64];   // dec upsample   [B,64,64,64]
// pre-transposed weights: [ci][tap][co]
__device__ __align__(16) float g_TW_E1[3*16*64];
__device__ __align__(16) float g_TW_E2[64*16*128];
__device__ __align__(16) float g_TW_E3[128*9*128];
__device__ __align__(16) float g_TW_R1A[128*9*32];
__device__ __align__(16) float g_TW_R2A[128*9*32];
__device__ __align__(16) float g_TW_DR1A[128*9*32];
__device__ __align__(16) float g_TW_DR2A[128*9*32];
__device__ __align__(16) float g_TW_DEC[64*9*128];          // flipped dw1
__device__ __align__(16) float g_TW_D2[128*16*64];
__device__ __align__(16) float g_TW_D3[64*16*4];            // co padded 3->4
__device__ float  g_ESQ[1024];
__device__ int    g_IDX[65536];
__device__ double g_PART[512];

// id -> buffer resolution done on DEVICE (avoids any host symbol-address API)
__device__ __forceinline__ float* gbuf(int id){
  switch(id){
    case 0: return g_A1; case 1: return g_A2; case 2: return g_A3;
    case 3: return g_T;  case 4: return g_Z;  case 5: return g_ZQ;
    case 6: return g_D1; case 7: return g_U1;
    case 10: return g_TW_E1;  case 11: return g_TW_E2;  case 12: return g_TW_E3;
    case 13: return g_TW_R1A; case 14: return g_TW_R2A; case 15: return g_TW_DR1A;
    case 16: return g_TW_DR2A;case 17: return g_TW_DEC; case 18: return g_TW_D2;
    default: return g_TW_D3;
  }
}
__device__ __forceinline__ const float* gbuf_c(int id, const float* ext){
  if (id < 0) return ext;
  return gbuf(id);
}

// ---------------- weight transposes ------------------------------------------
// w[co][ci][kk] -> T[ci][kk][co]
template<int CI,int CO,int KK>
__global__ void k_trA(const float* __restrict__ w, int out_id){
  float* T = gbuf(out_id);
  int t = blockIdx.x*256 + threadIdx.x;
  if (t >= CI*CO*KK) return;
  int co = t / (CI*KK);
  int r  = t % (CI*KK);
  int ci = r / KK, kk = r % KK;
  T[((size_t)ci*KK + kk)*CO + co] = w[t];
}
// w[ci][co][kk] -> T[ci][kk][COP]  (convT weights, co padded to COP)
template<int CI,int CO,int KK,int COP>
__global__ void k_trB(const float* __restrict__ w, int out_id){
  float* T = gbuf(out_id);
  int t = blockIdx.x*256 + threadIdx.x;
  if (t >= CI*CO*KK) return;
  int ci = t / (CO*KK);
  int r  = t % (CO*KK);
  int co = r / KK, kk = r % KK;
  T[((size_t)ci*KK + kk)*COP + co] = w[t];
}
// dw1 (64,128,3,3) flipped -> T[ci][kk][128]
__global__ void k_trF(const float* __restrict__ dw1){
  int t = blockIdx.x*256 + threadIdx.x;
  if (t >= 64*128*9) return;
  int ci = t / (128*9);
  int r  = t % (128*9);
  int co = r / 9, kk = r % 9;
  int ky = kk/3, kx = kk%3;
  g_TW_DEC[((size_t)ci*9 + (2-ky)*3 + (2-kx))*128 + co] = dw1[t];
}

// ---------------- 3x3 s1 p1 conv at 32x32, smem-staged, weights [ci][9][co] --
template<int CIN,int COUT,int COT,bool RIN,bool ROUT,bool HASB>
__global__ void __launch_bounds__(256,2)
k_conv3s(int in_id, int w_id, const float* __restrict__ bias, int out_id)
{
  __shared__ float sIn[34*40];       // 32x32 interior at (1,1), zero halo
  const float* in = gbuf_c(in_id, nullptr);
  const float* W  = gbuf_c(w_id, nullptr);
  float* out = gbuf(out_id);
  int co0 = blockIdx.x*COT;
  int b   = blockIdx.y;
  int tid = threadIdx.x;
  int tx = tid & 7, ty = tid >> 3;   // x0=4tx, y=ty
  int x0 = tx*4;

  for (int i=tid; i<34*40; i+=256) sIn[i] = 0.f;
  __syncthreads();

  float acc[COT][4];
  #pragma unroll
  for (int j=0;j<COT;j++){
    float bv = HASB ? __ldg(bias+co0+j) : 0.f;
    #pragma unroll
    for (int p=0;p<4;p++) acc[j][p]=bv;
  }

  const float* ipb = in + (size_t)b*CIN*1024;
  float* sp = sIn + ((tid>>3)+1)*40 + 1 + (tid&7)*4;
  for (int ci=0; ci<CIN; ci++){
    float4 v4 = __ldg(reinterpret_cast<const float4*>(ipb + (size_t)ci*1024) + tid);
    if (RIN){ v4.x=fmaxf(v4.x,0.f); v4.y=fmaxf(v4.y,0.f); v4.z=fmaxf(v4.z,0.f); v4.w=fmaxf(v4.w,0.f); }
    sp[0]=v4.x; sp[1]=v4.y; sp[2]=v4.z; sp[3]=v4.w;
    __syncthreads();
    const float* wp = W + (size_t)ci*9*COUT + co0;
    #pragma unroll
    for (int ky=0;ky<3;ky++){
      const float* row = sIn + (ty+ky)*40 + x0;
      float4 a = *reinterpret_cast<const float4*>(row);
      float v[6]; v[0]=a.x; v[1]=a.y; v[2]=a.z; v[3]=a.w; v[4]=row[4]; v[5]=row[5];
      #pragma unroll
      for (int kx=0;kx<3;kx++){
        #pragma unroll
        for (int j4=0;j4<COT/4;j4++){
          float4 wv = __ldg(reinterpret_cast<const float4*>(wp + (ky*3+kx)*COUT + j4*4));
          #pragma unroll
          for (int u=0;u<4;u++){
            float wu = (u==0)?wv.x:(u==1)?wv.y:(u==2)?wv.z:wv.w;
            acc[j4*4+u][0]=fmaf(wu,v[kx+0],acc[j4*4+u][0]);
            acc[j4*4+u][1]=fmaf(wu,v[kx+1],acc[j4*4+u][1]);
            acc[j4*4+u][2]=fmaf(wu,v[kx+2],acc[j4*4+u][2]);
            acc[j4*4+u][3]=fmaf(wu,v[kx+3],acc[j4*4+u][3]);
          }
        }
      }
    }
    __syncthreads();
  }
  #pragma unroll
  for (int j=0;j<COT;j++){
    float4 o = make_float4(acc[j][0],acc[j][1],acc[j][2],acc[j][3]);
    if (ROUT){ o.x=fmaxf(o.x,0.f); o.y=fmaxf(o.y,0.f); o.z=fmaxf(o.z,0.f); o.w=fmaxf(o.w,0.f); }
    *reinterpret_cast<float4*>(out + ((size_t)(b*COUT+co0+j)*32 + ty)*32 + x0) = o;
  }
}

// ---------------- 4x4 s2 p1 conv, smem-staged, spatially tiled (out 32x32) ---
template<int CIN,int COUT,int HIN,int COT>
__global__ void __launch_bounds__(256,2)
k_conv4s(const float* __restrict__ ext_in, int in_id, int w_id,
         const float* __restrict__ bias, int out_id)
{
  constexpr int HOUT = HIN/2;
  constexpr int XT   = HOUT/32;
  __shared__ float sIn[66*72];
  const float* in = gbuf_c(in_id, ext_in);
  const float* W  = gbuf_c(w_id, nullptr);
  float* out = gbuf(out_id);
  int co0 = blockIdx.x*COT;
  int oy0 = (blockIdx.y/XT)*32, ox0 = (blockIdx.y%XT)*32;
  int b = blockIdx.z;
  int tid = threadIdx.x;
  int tx = tid & 7, ty = tid >> 3;
  int x0 = tx*4;

  float acc[COT][4];
  #pragma unroll
  for (int j=0;j<COT;j++){
    float bv = __ldg(bias+co0+j);
    #pragma unroll
    for (int p=0;p<4;p++) acc[j][p]=bv;
  }

  int iy0 = oy0*2 - 1, ix0 = ox0*2 - 1;
  for (int ci=0; ci<CIN; ci++){
    const float* ip = in + (size_t)(b*CIN+ci)*HIN*HIN;
    for (int s=tid; s<66*66; s+=256){
      int r = s/66, c = s%66;
      int giy = iy0 + r, gix = ix0 + c;
      float v = 0.f;
      if (giy>=0 && giy<HIN && gix>=0 && gix<HIN) v = __ldg(ip + (size_t)giy*HIN + gix);
      sIn[r*72 + c] = v;
    }
    __syncthreads();
    const float* wp = W + (size_t)ci*16*COUT + co0;
    #pragma unroll
    for (int ky=0;ky<4;ky++){
      const float* row = sIn + (2*ty+ky)*72 + 2*x0;
      float4 a  = *reinterpret_cast<const float4*>(row);
      float4 bq = *reinterpret_cast<const float4*>(row+4);
      float v[10]; v[0]=a.x;v[1]=a.y;v[2]=a.z;v[3]=a.w;
      v[4]=bq.x;v[5]=bq.y;v[6]=bq.z;v[7]=bq.w;v[8]=row[8];v[9]=row[9];
      #pragma unroll
      for (int kx=0;kx<4;kx++){
        #pragma unroll
        for (int j4=0;j4<COT/4;j4++){
          float4 wv = __ldg(reinterpret_cast<const float4*>(wp + (ky*4+kx)*COUT + j4*4));
          #pragma unroll
          for (int u=0;u<4;u++){
            float wu = (u==0)?wv.x:(u==1)?wv.y:(u==2)?wv.z:wv.w;
            acc[j4*4+u][0]=fmaf(wu,v[kx+0],acc[j4*4+u][0]);
            acc[j4*4+u][1]=fmaf(wu,v[kx+2],acc[j4*4+u][1]);
            acc[j4*4+u][2]=fmaf(wu,v[kx+4],acc[j4*4+u][2]);
            acc[j4*4+u][3]=fmaf(wu,v[kx+6],acc[j4*4+u][3]);
          }
        }
      }
    }
    __syncthreads();
  }
  #pragma unroll
  for (int j=0;j<COT;j++){
    float4 o = make_float4(fmaxf(acc[j][0],0.f),fmaxf(acc[j][1],0.f),
                           fmaxf(acc[j][2],0.f),fmaxf(acc[j][3],0.f));
    *reinterpret_cast<float4*>(out + ((size_t)(b*COUT+co0+j)*HOUT + oy0+ty)*HOUT + ox0+x0) = o;
  }
}

// ---------------- 1x1 conv, residual-add into x ------------------------------
template<int CIN,int COUT>
__global__ void k_res1x1(int t_id, const float* __restrict__ w, int x_id)
{
  const float* t = gbuf_c(t_id, nullptr);
  float* x = gbuf(x_id);
  int co0 = blockIdx.x*4;
  int b = blockIdx.y;
  int p0 = threadIdx.x*8;
  float acc[4][8];
  #pragma unroll
  for (int j=0;j<4;j++)
    #pragma unroll
    for (int u=0;u<8;u++) acc[j][u]=0.f;
  for (int ci=0;ci<CIN;ci++){
    const float* ip = t + (size_t)(b*CIN+ci)*1024 + p0;
    float4 va = *reinterpret_cast<const float4*>(ip);
    float4 vb = *reinterpret_cast<const float4*>(ip+4);
    #pragma unroll
    for (int j=0;j<4;j++){
      float wv = __ldg(w + (size_t)(co0+j)*CIN + ci);
      acc[j][0]=fmaf(wv,va.x,acc[j][0]); acc[j][1]=fmaf(wv,va.y,acc[j][1]);
      acc[j][2]=fmaf(wv,va.z,acc[j][2]); acc[j][3]=fmaf(wv,va.w,acc[j][3]);
      acc[j][4]=fmaf(wv,vb.x,acc[j][4]); acc[j][5]=fmaf(wv,vb.y,acc[j][5]);
      acc[j][6]=fmaf(wv,vb.z,acc[j][6]); acc[j][7]=fmaf(wv,vb.w,acc[j][7]);
    }
  }
  #pragma unroll
  for (int j=0;j<4;j++){
    float* op = x + (size_t)(b*COUT+co0+j)*1024 + p0;
    #pragma unroll
    for (int u=0;u<8;u++) op[u] += acc[j][u];
  }
}

// ---------------- pre-quant 1x1: relu(in) -> z (NHWC) ------------------------
__global__ void k_pq(int in_id, const float* __restrict__ w,
                     const float* __restrict__ bias)
{
  const float* h = gbuf_c(in_id, nullptr);
  int d0 = blockIdx.x*4;
  int b = blockIdx.y;
  int p0 = threadIdx.x*8;
  float acc[4][8];
  #pragma unroll
  for (int j=0;j<4;j++){ float bv=__ldg(bias+d0+j);
    #pragma unroll
    for (int u=0;u<8;u++) acc[j][u]=bv; }
  for (int ci=0;ci<128;ci++){
    const float* ip = h + (size_t)(b*128+ci)*1024 + p0;
    float4 va = *reinterpret_cast<const float4*>(ip);
    float4 vb = *reinterpret_cast<const float4*>(ip+4);
    va.x=fmaxf(va.x,0.f); va.y=fmaxf(va.y,0.f); va.z=fmaxf(va.z,0.f); va.w=fmaxf(va.w,0.f);
    vb.x=fmaxf(vb.x,0.f); vb.y=fmaxf(vb.y,0.f); vb.z=fmaxf(vb.z,0.f); vb.w=fmaxf(vb.w,0.f);
    #pragma unroll
    for (int j=0;j<4;j++){
      float wv = __ldg(w + (size_t)(d0+j)*128 + ci);
      acc[j][0]=fmaf(wv,va.x,acc[j][0]); acc[j][1]=fmaf(wv,va.y,acc[j][1]);
      acc[j][2]=fmaf(wv,va.z,acc[j][2]); acc[j][3]=fmaf(wv,va.w,acc[j][3]);
      acc[j][4]=fmaf(wv,vb.x,acc[j][4]); acc[j][5]=fmaf(wv,vb.y,acc[j][5]);
      acc[j][6]=fmaf(wv,vb.z,acc[j][6]); acc[j][7]=fmaf(wv,vb.w,acc[j][7]);
    }
  }
  #pragma unroll
  for (int p=0;p<8;p++){
    float4 o = make_float4(acc[0][p],acc[1][p],acc[2][p],acc[3][p]);
    *reinterpret_cast<float4*>(g_Z + (size_t)(b*1024+p0+p)*64 + d0) = o;
  }
}

// ---------------- codebook squared norms -------------------------------------
__global__ void k_esq(const float* __restrict__ emb){
  int k = blockIdx.x*blockDim.x + threadIdx.x;
  if (k >= 1024) return;
  const float4* e = reinterpret_cast<const float4*>(emb + (size_t)k*64);
  float s = 0.f;
  #pragma unroll
  for (int i=0;i<16;i++){
    float4 v = e[i];
    s = fmaf(v.x,v.x,fmaf(v.y,v.y,fmaf(v.z,v.z,fmaf(v.w,v.w,s))));
  }
  g_ESQ[k] = s;
}

// ---------------- VQ: argmin, gather to NCHW, loss partials ------------------
__global__ void k_vq(const float* __restrict__ emb){
  __shared__ __align__(16) float sE[128*64];
  __shared__ float sQ[128];
  __shared__ double sred[128];
  int tid = threadIdx.x;
  int n = blockIdx.x*128 + tid;
  int b = n >> 10, p = n & 1023;
  float zr[64];
  {
    const float4* zp = reinterpret_cast<const float4*>(g_Z + (size_t)n*64);
    float4* zr4 = reinterpret_cast<float4*>(zr);
    #pragma unroll
    for (int i=0;i<16;i++) zr4[i] = zp[i];
  }
  float best = FLT_MAX; int bi = 0;
  for (int c=0;c<8;c++){
    const float4* src = reinterpret_cast<const float4*>(emb) + (size_t)c*2048;
    float4* dst = reinterpret_cast<float4*>(sE);
    #pragma unroll
    for (int r=0;r<16;r++) dst[tid + r*128] = src[tid + r*128];
    sQ[tid] = g_ESQ[c*128+tid];
    __syncthreads();
    for (int kk=0;kk<128;kk++){
      const float4* e = reinterpret_cast<const float4*>(sE + kk*64);
      float d0=0.f,d1=0.f,d2=0.f,d3=0.f;
      #pragma unroll
      for (int i=0;i<16;i++){
        float4 ev = e[i];
        float4 zv = reinterpret_cast<float4*>(zr)[i];
        d0 = fmaf(ev.x,zv.x,d0); d1 = fmaf(ev.y,zv.y,d1);
        d2 = fmaf(ev.z,zv.z,d2); d3 = fmaf(ev.w,zv.w,d3);
      }
      float sc = sQ[kk] - 2.f*((d0+d1)+(d2+d3));
      if (sc < best){ best = sc; bi = c*128+kk; }   // strict < : first min (jnp.argmin)
    }
    __syncthreads();
  }
  g_IDX[n] = bi;
  const float* er = emb + (size_t)bi*64;
  float ls = 0.f;
  #pragma unroll
  for (int d=0; d<64; d++){
    float e = __ldg(er+d);
    g_ZQ[(size_t)(b*64+d)*1024 + p] = e;
    float df = e - zr[d];
    ls = fmaf(df,df,ls);
  }
  sred[tid] = (double)ls;
  __syncthreads();
  #pragma unroll
  for (int s=64;s>0;s>>=1){
    if (tid<s) sred[tid] += sred[tid+s];
    __syncthreads();
  }
  if (tid==0) g_PART[blockIdx.x] = sred[0];
}

// ---------------- ConvTranspose 4x4 s2 p1: 128@32 -> 64@64, relu in+out ------
__global__ void __launch_bounds__(256,2)
k_convT2s(const float* __restrict__ bias)
{
  constexpr int COT = 16;
  __shared__ float sIn[10*40];       // rows yq0-1..yq0+8, cols halo (offset 1)
  int co0 = blockIdx.x*COT;
  int yq0 = blockIdx.y*8;
  int b   = blockIdx.z;
  int tid = threadIdx.x;
  int tx = tid & 31, ty = tid >> 5;  // xq=tx (0..31), yq=yq0+ty

  float acc[COT][4];
  #pragma unroll
  for (int j=0;j<COT;j++)
    #pragma unroll
    for (int q=0;q<4;q++) acc[j][q]=0.f;

  const float* ipb = g_D1 + (size_t)b*128*1024;
  for (int ci=0; ci<128; ci++){
    const float* ip = ipb + (size_t)ci*1024;
    for (int s=tid; s<340; s+=256){
      int r = s/34, c = s%34;
      int giy = yq0-1+r, gix = c-1;
      float v = (giy>=0 && giy<32 && gix>=0 && gix<32) ? fmaxf(__ldg(ip+giy*32+gix),0.f) : 0.f;
      sIn[r*40 + c] = v;
    }
    __syncthreads();
    float r3[3][3];
    #pragma unroll
    for (int dy=0;dy<3;dy++)
      #pragma unroll
      for (int dx=0;dx<3;dx++)
        r3[dy][dx] = sIn[(ty+dy)*40 + tx+dx];
    const float* wp = g_TW_D2 + (size_t)ci*16*64 + co0;
    #pragma unroll
    for (int ky=0;ky<4;ky++){
      #pragma unroll
      for (int kx=0;kx<4;kx++){
        float rv = r3[(4-ky)>>1][(4-kx)>>1];
        const int pp = (((ky&1)^1)<<1) | ((kx&1)^1);
        #pragma unroll
        for (int j4=0;j4<COT/4;j4++){
          float4 wv = __ldg(reinterpret_cast<const float4*>(wp + (ky*4+kx)*64 + j4*4));
          acc[j4*4+0][pp]=fmaf(wv.x,rv,acc[j4*4+0][pp]);
          acc[j4*4+1][pp]=fmaf(wv.y,rv,acc[j4*4+1][pp]);
          acc[j4*4+2][pp]=fmaf(wv.z,rv,acc[j4*4+2][pp]);
          acc[j4*4+3][pp]=fmaf(wv.w,rv,acc[j4*4+3][pp]);
        }
      }
    }
    __syncthreads();
  }
  int yq = yq0 + ty;
  #pragma unroll
  for (int j=0;j<COT;j++){
    float bv = __ldg(bias+co0+j);
    float* op = g_U1 + (size_t)(b*64+co0+j)*4096;
    float2 e0 = make_float2(fmaxf(acc[j][0]+bv,0.f), fmaxf(acc[j][1]+bv,0.f));
    float2 e1 = make_float2(fmaxf(acc[j][2]+bv,0.f), fmaxf(acc[j][3]+bv,0.f));
    *reinterpret_cast<float2*>(op + (2*yq+0)*64 + 2*tx) = e0;
    *reinterpret_cast<float2*>(op + (2*yq+1)*64 + 2*tx) = e1;
  }
}

// ---------------- ConvTranspose 4x4 s2 p1: 64@64 -> 3@128 (recon) ------------
__global__ void __launch_bounds__(256,2)
k_convT3s(const float* __restrict__ bias, float* __restrict__ out)
{
  __shared__ float sIn[10*40];
  int xq0 = blockIdx.x*32;
  int yq0 = blockIdx.y*8;
  int b   = blockIdx.z;
  int tid = threadIdx.x;
  int tx = tid & 31, ty = tid >> 5;

  float acc[4][4];
  #pragma unroll
  for (int j=0;j<4;j++)
    #pragma unroll
    for (int q=0;q<4;q++) acc[j][q]=0.f;

  const float* ipb = g_U1 + (size_t)b*64*4096;
  for (int ci=0; ci<64; ci++){
    const float* ip = ipb + (size_t)ci*4096;
    for (int s=tid; s<340; s+=256){
      int r = s/34, c = s%34;
      int giy = yq0-1+r, gix = xq0-1+c;
      float v = (giy>=0 && giy<64 && gix>=0 && gix<64) ? __ldg(ip+giy*64+gix) : 0.f;
      sIn[r*40 + c] = v;
    }
    __syncthreads();
    float r3[3][3];
    #pragma unroll
    for (int dy=0;dy<3;dy++)
      #pragma unroll
      for (int dx=0;dx<3;dx++)
        r3[dy][dx] = sIn[(ty+dy)*40 + tx+dx];
    const float* wp = g_TW_D3 + (size_t)ci*16*4;
    #pragma unroll
    for (int ky=0;ky<4;ky++){
      #pragma unroll
      for (int kx=0;kx<4;kx++){
        float rv = r3[(4-ky)>>1][(4-kx)>>1];
        const int pp = (((ky&1)^1)<<1) | ((kx&1)^1);
        float4 wv = __ldg(reinterpret_cast<const float4*>(wp + (ky*4+kx)*4));
        acc[0][pp]=fmaf(wv.x,rv,acc[0][pp]);
        acc[1][pp]=fmaf(wv.y,rv,acc[1][pp]);
        acc[2][pp]=fmaf(wv.z,rv,acc[2][pp]);
      }
    }
    __syncthreads();
  }
  int yq = yq0 + ty, xq = xq0 + tx;
  #pragma unroll
  for (int j=0;j<3;j++){
    float bv = __ldg(bias+j);
    float* op = out + (size_t)(b*3+j)*16384;
    float2 e0 = make_float2(acc[j][0]+bv, acc[j][1]+bv);
    float2 e1 = make_float2(acc[j][2]+bv, acc[j][3]+bv);
    *reinterpret_cast<float2*>(op + (2*yq+0)*128 + 2*xq) = e0;
    *reinterpret_cast<float2*>(op + (2*yq+1)*128 + 2*xq) = e1;
  }
}

// ---------------- finalize: idx as float + deterministic loss ----------------
__global__ void k_final(float* __restrict__ out){
  int t = blockIdx.x*blockDim.x + threadIdx.x;
  if (t < 65536) out[3145730 + t] = (float)g_IDX[t];
  if (t == 0){
    double s = 0.0;
    for (int i=0;i<512;i++) s += g_PART[i];
    float m = (float)(s / 4194304.0);
    out[3145728] = m;   // codebook_loss
    out[3145729] = m;   // commitment_loss (identical value)
  }
}

// ---------------- launcher ---------------------------------------------------
extern "C" void kernel_launch(void* const* d_in, const int* in_sizes, int n_in,
                              void* d_out, int out_size)
{
  const float* patch=(const float*)d_in[0];
  const float* ew1=(const float*)d_in[1];  const float* eb1=(const float*)d_in[2];
  const float* ew2=(const float*)d_in[3];  const float* eb2=(const float*)d_in[4];
  const float* ew3=(const float*)d_in[5];  const float* eb3=(const float*)d_in[6];
  const float* er1a=(const float*)d_in[7]; const float* er1b=(const float*)d_in[8];
  const float* er2a=(const float*)d_in[9]; const float* er2b=(const float*)d_in[10];
  const float* pqw=(const float*)d_in[11]; const float* pqb=(const float*)d_in[12];
  const float* emb=(const float*)d_in[13];
  const float* dw1=(const float*)d_in[14]; const float* db1=(const float*)d_in[15];
  const float* dr1a=(const float*)d_in[16];const float* dr1b=(const float*)d_in[17];
  const float* dr2a=(const float*)d_in[18];const float* dr2b=(const float*)d_in[19];
  const float* dw2=(const float*)d_in[20]; const float* db2=(const float*)d_in[21];
  const float* dw3=(const float*)d_in[22]; const float* db3=(const float*)d_in[23];
  float* out = (float*)d_out;
  (void)in_sizes; (void)n_in; (void)out_size;

  // codebook norms + weight pre-transposes (cheap, every launch)
  k_esq<<<4,256>>>(emb);
  k_trA<3,64,16>  <<<12,256>>>(ew1, 10);
  k_trA<64,128,16><<<512,256>>>(ew2, 11);
  k_trA<128,128,9><<<576,256>>>(ew3, 12);
  k_trA<128,32,9> <<<144,256>>>(er1a, 13);
  k_trA<128,32,9> <<<144,256>>>(er2a, 14);
  k_trA<128,32,9> <<<144,256>>>(dr1a, 15);
  k_trA<128,32,9> <<<144,256>>>(dr2a, 16);
  k_trF<<<288,256>>>(dw1);
  k_trB<128,64,16,64><<<512,256>>>(dw2, 18);
  k_trB<64,3,16,4>   <<<12,256>>>(dw3, 19);

  // encoder
  k_conv4s<3,64,128,16> <<<dim3(4,4,NB),256>>>(patch, -1, 10, eb1, 0);
  k_conv4s<64,128,64,16><<<dim3(8,1,NB),256>>>(nullptr, 0, 11, eb2, 1);
  k_conv3s<128,128,16,false,false,true><<<dim3(8,NB),256>>>(1, 12, eb3, 2);
  // residual block 1
  k_conv3s<128,32,8,true,true,false><<<dim3(4,NB),256>>>(2, 13, nullptr, 3);
  k_res1x1<32,128><<<dim3(32,NB),128>>>(3, er1b, 2);
  // residual block 2
  k_conv3s<128,32,8,true,true,false><<<dim3(4,NB),256>>>(2, 14, nullptr, 3);
  k_res1x1<32,128><<<dim3(32,NB),128>>>(3, er2b, 2);
  // pre-quant (relu fused into input)
  k_pq<<<dim3(16,NB),128>>>(2, pqw, pqb);
  // vector quantization
  k_vq<<<512,128>>>(emb);

  // decoder
  k_conv3s<64,128,16,false,false,true><<<dim3(8,NB),256>>>(5, 17, db1, 6);
  k_conv3s<128,32,8,true,true,false><<<dim3(4,NB),256>>>(6, 15, nullptr, 3);
  k_res1x1<32,128><<<dim3(32,NB),128>>>(3, dr1b, 6);
  k_conv3s<128,32,8,true,true,false><<<dim3(4,NB),256>>>(6, 16, nullptr, 3);
  k_res1x1<32,128><<<dim3(32,NB),128>>>(3, dr2b, 6);
  k_convT2s<<<dim3(4,4,NB),256>>>(db2);
  k_convT3s<<<dim3(2,8,NB),256>>>(db3, out);

  // losses + indices
  k_final<<<256,256>>>(out);
}

// round 8
// speedup vs baseline: 1.1760x; 1.0581x over previous
#include <cuda_runtime.h>
#include <cfloat>
#include <cstddef>

#define NB 64   // batch

typedef unsigned long long u64;

// ---- packed f32x2 helpers ---------------------------------------------------
__device__ __forceinline__ u64 pk2(float lo, float hi){
  u64 r; asm("mov.b64 %0,{%1,%2};" : "=l"(r) : "f"(lo), "f"(hi)); return r;
}
__device__ __forceinline__ float2 up2(u64 v){
  float2 f; asm("mov.b64 {%0,%1},%2;" : "=f"(f.x), "=f"(f.y) : "l"(v)); return f;
}
__device__ __forceinline__ void fma2(u64 &d, u64 a, u64 b){
  asm("fma.rn.f32x2 %0,%1,%2,%0;" : "+l"(d) : "l"(a), "l"(b));
}

// ---------------- scratch buffers (device globals; no allocations) ----------
__device__ __align__(16) float g_A1[(size_t)NB*64*64*64];   // enc conv1 out
__device__ __align__(16) float g_A2[(size_t)NB*128*32*32];  // enc conv2 out
__device__ __align__(16) float g_A3[(size_t)NB*128*32*32];  // enc conv3/res
__device__ __align__(16) float g_T [(size_t)NB*32*32*32];   // res 3x3 temp
__device__ __align__(16) float g_Z [(size_t)NB*32*32*64];   // z NHWC
__device__ __align__(16) float g_ZQ[(size_t)NB*64*32*32];   // z_q NCHW
__device__ __align__(16) float g_D1[(size_t)NB*128*32*32];  // dec trunk
__device__ __align__(16) float g_U1[(size_t)NB*64*64*64];   // dec upsample
// pre-transposed weights: [ci][tap][co]
__device__ __align__(16) float g_TW_E1[3*16*64];
__device__ __align__(16) float g_TW_E2[64*16*128];
__device__ __align__(16) float g_TW_E3[128*9*128];
__device__ __align__(16) float g_TW_R1A[128*9*32];
__device__ __align__(16) float g_TW_R2A[128*9*32];
__device__ __align__(16) float g_TW_DR1A[128*9*32];
__device__ __align__(16) float g_TW_DR2A[128*9*32];
__device__ __align__(16) float g_TW_DEC[64*9*128];          // flipped dw1
__device__ __align__(16) float g_TW_D2[128*16*64];
__device__ __align__(16) float g_TW_D3[64*16*4];            // co padded 3->4
__device__ float  g_ESQ[1024];
__device__ int    g_IDX[65536];
__device__ double g_PART[512];

__device__ __forceinline__ float* gbuf(int id){
  switch(id){
    case 0: return g_A1; case 1: return g_A2; case 2: return g_A3;
    case 3: return g_T;  case 4: return g_Z;  case 5: return g_ZQ;
    case 6: return g_D1; case 7: return g_U1;
    case 10: return g_TW_E1;  case 11: return g_TW_E2;  case 12: return g_TW_E3;
    case 13: return g_TW_R1A; case 14: return g_TW_R2A; case 15: return g_TW_DR1A;
    case 16: return g_TW_DR2A;case 17: return g_TW_DEC; case 18: return g_TW_D2;
    default: return g_TW_D3;
  }
}
__device__ __forceinline__ const float* gbuf_c(int id, const float* ext){
  if (id < 0) return ext;
  return gbuf(id);
}

// ---------------- merged prep: esq + all weight transposes -------------------
__device__ __forceinline__ void trA_i(const float* __restrict__ w, float* T,
                                      int CI,int CO,int KK,int t){
  int co = t/(CI*KK); int r = t%(CI*KK); int ci = r/KK, kk = r%KK;
  T[((size_t)ci*KK+kk)*CO+co] = w[t];
}
__device__ __forceinline__ void trB_i(const float* __restrict__ w, float* T,
                                      int CI,int CO,int KK,int COP,int t){
  int ci = t/(CO*KK); int r = t%(CO*KK); int co = r/KK, kk = r%KK;
  T[((size_t)ci*KK+kk)*COP+co] = w[t];
}

__global__ void k_prep(const float* __restrict__ emb,
                       const float* __restrict__ ew1, const float* __restrict__ ew2,
                       const float* __restrict__ ew3,
                       const float* __restrict__ er1a, const float* __restrict__ er2a,
                       const float* __restrict__ dr1a, const float* __restrict__ dr2a,
                       const float* __restrict__ dw1, const float* __restrict__ dw2,
                       const float* __restrict__ dw3)
{
  int t = blockIdx.x*256 + threadIdx.x;
  if (t < 1024){
    const float4* e = reinterpret_cast<const float4*>(emb + (size_t)t*64);
    float s = 0.f;
    #pragma unroll
    for (int i=0;i<16;i++){
      float4 v = e[i];
      s = fmaf(v.x,v.x,fmaf(v.y,v.y,fmaf(v.z,v.z,fmaf(v.w,v.w,s))));
    }
    g_ESQ[t] = s; return;
  } t -= 1024;
  if (t < 3072){ trA_i(ew1, g_TW_E1, 3,64,16, t); return; } t -= 3072;
  if (t < 131072){ trA_i(ew2, g_TW_E2, 64,128,16, t); return; } t -= 131072;
  if (t < 147456){ trA_i(ew3, g_TW_E3, 128,128,9, t); return; } t -= 147456;
  if (t < 36864){ trA_i(er1a, g_TW_R1A, 128,32,9, t); return; } t -= 36864;
  if (t < 36864){ trA_i(er2a, g_TW_R2A, 128,32,9, t); return; } t -= 36864;
  if (t < 36864){ trA_i(dr1a, g_TW_DR1A, 128,32,9, t); return; } t -= 36864;
  if (t < 36864){ trA_i(dr2a, g_TW_DR2A, 128,32,9, t); return; } t -= 36864;
  if (t < 73728){
    int ci = t/(128*9); int r = t%(128*9); int co = r/9, kk = r%9;
    int ky = kk/3, kx = kk%3;
    g_TW_DEC[((size_t)ci*9 + (2-ky)*3 + (2-kx))*128 + co] = dw1[t]; return;
  } t -= 73728;
  if (t < 131072){ trB_i(dw2, g_TW_D2, 128,64,16,64, t); return; } t -= 131072;
  if (t < 3072){ trB_i(dw3, g_TW_D3, 64,3,16,4, t); }
}

// ---------------- 3x3 s1 p1 conv at 32x32, f32x2, double-buffered ------------
template<int CIN,int COUT,int COT,bool RIN,bool ROUT,bool HASB>
__global__ void __launch_bounds__(256,2)
k_conv3s(int in_id, int w_id, const float* __restrict__ bias, int out_id)
{
  constexpr int CP = COT/2;
  __shared__ float sIn[2][34*40];
  const float* in = gbuf_c(in_id, nullptr);
  const float* W  = gbuf_c(w_id, nullptr);
  float* out = gbuf(out_id);
  int co0 = blockIdx.x*COT;
  int b   = blockIdx.y;
  int tid = threadIdx.x;
  int tx = tid & 7, ty = tid >> 3;
  int x0 = tx*4;

  for (int i=tid; i<34*40; i+=256){ sIn[0][i]=0.f; sIn[1][i]=0.f; }
  __syncthreads();

  u64 acc[CP][4];
  #pragma unroll
  for (int j=0;j<CP;j++){
    u64 bp = HASB ? pk2(__ldg(bias+co0+2*j), __ldg(bias+co0+2*j+1)) : 0ull;
    #pragma unroll
    for (int p=0;p<4;p++) acc[j][p] = bp;
  }

  const float* ipb = in + (size_t)b*CIN*1024;
  float4 v4 = __ldg(reinterpret_cast<const float4*>(ipb) + tid);
  if (RIN){ v4.x=fmaxf(v4.x,0.f); v4.y=fmaxf(v4.y,0.f); v4.z=fmaxf(v4.z,0.f); v4.w=fmaxf(v4.w,0.f); }

  int pb = 0;
  for (int ci=0; ci<CIN; ci++){
    float* sp = &sIn[pb][(ty+1)*40 + 1 + x0];
    sp[0]=v4.x; sp[1]=v4.y; sp[2]=v4.z; sp[3]=v4.w;
    __syncthreads();
    if (ci+1 < CIN){
      v4 = __ldg(reinterpret_cast<const float4*>(ipb + (size_t)(ci+1)*1024) + tid);
      if (RIN){ v4.x=fmaxf(v4.x,0.f); v4.y=fmaxf(v4.y,0.f); v4.z=fmaxf(v4.z,0.f); v4.w=fmaxf(v4.w,0.f); }
    }
    const float* wp = W + (size_t)ci*9*COUT + co0;
    #pragma unroll
    for (int ky=0;ky<3;ky++){
      const float* row = &sIn[pb][(ty+ky)*40 + x0];
      float4 a = *reinterpret_cast<const float4*>(row);
      float e4 = row[4], e5 = row[5];
      u64 vb[6];
      vb[0]=pk2(a.x,a.x); vb[1]=pk2(a.y,a.y); vb[2]=pk2(a.z,a.z);
      vb[3]=pk2(a.w,a.w); vb[4]=pk2(e4,e4);  vb[5]=pk2(e5,e5);
      #pragma unroll
      for (int kx=0;kx<3;kx++){
        const ulonglong2* wq = reinterpret_cast<const ulonglong2*>(wp + (ky*3+kx)*COUT);
        #pragma unroll
        for (int j2=0;j2<CP/2;j2++){
          ulonglong2 wv = __ldg(wq + j2);
          #pragma unroll
          for (int p=0;p<4;p++){
            fma2(acc[2*j2  ][p], wv.x, vb[kx+p]);
            fma2(acc[2*j2+1][p], wv.y, vb[kx+p]);
          }
        }
      }
    }
    pb ^= 1;
  }
  #pragma unroll
  for (int j=0;j<CP;j++){
    float2 f0=up2(acc[j][0]), f1=up2(acc[j][1]), f2=up2(acc[j][2]), f3=up2(acc[j][3]);
    float4 oe = make_float4(f0.x,f1.x,f2.x,f3.x);
    float4 oo = make_float4(f0.y,f1.y,f2.y,f3.y);
    if (ROUT){
      oe.x=fmaxf(oe.x,0.f); oe.y=fmaxf(oe.y,0.f); oe.z=fmaxf(oe.z,0.f); oe.w=fmaxf(oe.w,0.f);
      oo.x=fmaxf(oo.x,0.f); oo.y=fmaxf(oo.y,0.f); oo.z=fmaxf(oo.z,0.f); oo.w=fmaxf(oo.w,0.f);
    }
    *reinterpret_cast<float4*>(out + ((size_t)(b*COUT+co0+2*j  )*32 + ty)*32 + x0) = oe;
    *reinterpret_cast<float4*>(out + ((size_t)(b*COUT+co0+2*j+1)*32 + ty)*32 + x0) = oo;
  }
}

// ---------------- 4x4 s2 p1 conv, f32x2, double-buffered ---------------------
template<int CIN,int COUT,int HIN,int COT>
__global__ void __launch_bounds__(256,2)
k_conv4s(const float* __restrict__ ext_in, int in_id, int w_id,
         const float* __restrict__ bias, int out_id)
{
  constexpr int CP = COT/2;
  constexpr int HOUT = HIN/2;
  constexpr int XT   = HOUT/32;
  __shared__ float sIn[2][66*72];
  const float* in = gbuf_c(in_id, ext_in);
  const float* W  = gbuf_c(w_id, nullptr);
  float* out = gbuf(out_id);
  int co0 = blockIdx.x*COT;
  int oy0 = (blockIdx.y/XT)*32, ox0 = (blockIdx.y%XT)*32;
  int b = blockIdx.z;
  int tid = threadIdx.x;
  int tx = tid & 7, ty = tid >> 3;
  int x0 = tx*4;

  u64 acc[CP][4];
  #pragma unroll
  for (int j=0;j<CP;j++){
    u64 bp = pk2(__ldg(bias+co0+2*j), __ldg(bias+co0+2*j+1));
    #pragma unroll
    for (int p=0;p<4;p++) acc[j][p] = bp;
  }

  int iy0 = oy0*2 - 1, ix0 = ox0*2 - 1;
  float sreg[18];
  {
    const float* ip = in + (size_t)b*CIN*HIN*HIN;
    #pragma unroll
    for (int t=0;t<18;t++){
      int s = tid + t*256; float v = 0.f;
      if (s < 4356){
        int r = s/66, c = s - r*66;
        int giy = iy0 + r, gix = ix0 + c;
        if (giy>=0 && giy<HIN && gix>=0 && gix<HIN) v = __ldg(ip + (size_t)giy*HIN + gix);
      }
      sreg[t] = v;
    }
  }
  int pb = 0;
  for (int ci=0; ci<CIN; ci++){
    #pragma unroll
    for (int t=0;t<18;t++){
      int s = tid + t*256;
      if (s < 4356){ int r = s/66, c = s - r*66; sIn[pb][r*72 + c] = sreg[t]; }
    }
    __syncthreads();
    if (ci+1 < CIN){
      const float* ip = in + (size_t)(b*CIN+ci+1)*HIN*HIN;
      #pragma unroll
      for (int t=0;t<18;t++){
        int s = tid + t*256; float v = 0.f;
        if (s < 4356){
          int r = s/66, c = s - r*66;
          int giy = iy0 + r, gix = ix0 + c;
          if (giy>=0 && giy<HIN && gix>=0 && gix<HIN) v = __ldg(ip + (size_t)giy*HIN + gix);
        }
        sreg[t] = v;
      }
    }
    const float* wp = W + (size_t)ci*16*COUT + co0;
    #pragma unroll
    for (int ky=0;ky<4;ky++){
      const float* row = &sIn[pb][(2*ty+ky)*72 + 2*x0];
      float4 a  = *reinterpret_cast<const float4*>(row);
      float4 bq = *reinterpret_cast<const float4*>(row+4);
      float e8 = row[8], e9 = row[9];
      u64 vb[10];
      vb[0]=pk2(a.x,a.x); vb[1]=pk2(a.y,a.y); vb[2]=pk2(a.z,a.z); vb[3]=pk2(a.w,a.w);
      vb[4]=pk2(bq.x,bq.x); vb[5]=pk2(bq.y,bq.y); vb[6]=pk2(bq.z,bq.z); vb[7]=pk2(bq.w,bq.w);
      vb[8]=pk2(e8,e8); vb[9]=pk2(e9,e9);
      #pragma unroll
      for (int kx=0;kx<4;kx++){
        const ulonglong2* wq = reinterpret_cast<const ulonglong2*>(wp + (ky*4+kx)*COUT);
        #pragma unroll
        for (int j2=0;j2<CP/2;j2++){
          ulonglong2 wv = __ldg(wq + j2);
          #pragma unroll
          for (int p=0;p<4;p++){
            fma2(acc[2*j2  ][p], wv.x, vb[kx+2*p]);
            fma2(acc[2*j2+1][p], wv.y, vb[kx+2*p]);
          }
        }
      }
    }
    pb ^= 1;
  }
  #pragma unroll
  for (int j=0;j<CP;j++){
    float2 f0=up2(acc[j][0]), f1=up2(acc[j][1]), f2=up2(acc[j][2]), f3=up2(acc[j][3]);
    float4 oe = make_float4(fmaxf(f0.x,0.f),fmaxf(f1.x,0.f),fmaxf(f2.x,0.f),fmaxf(f3.x,0.f));
    float4 oo = make_float4(fmaxf(f0.y,0.f),fmaxf(f1.y,0.f),fmaxf(f2.y,0.f),fmaxf(f3.y,0.f));
    *reinterpret_cast<float4*>(out + ((size_t)(b*COUT+co0+2*j  )*HOUT + oy0+ty)*HOUT + ox0+x0) = oe;
    *reinterpret_cast<float4*>(out + ((size_t)(b*COUT+co0+2*j+1)*HOUT + oy0+ty)*HOUT + ox0+x0) = oo;
  }
}

// ---------------- 1x1 conv residual-add, smem weights, input read once -------
__global__ void __launch_bounds__(256)
k_res1x1v(int t_id, const float* __restrict__ w, int x_id)
{
  __shared__ float sw[128*32];
  const float* t = gbuf_c(t_id, nullptr);
  float* x = gbuf(x_id);
  int b = blockIdx.y, p = blockIdx.x*256 + threadIdx.x;
  for (int i=threadIdx.x; i<4096; i+=256) sw[i] = __ldg(w+i);
  __syncthreads();
  float rv[32];
  #pragma unroll
  for (int ci=0;ci<32;ci++) rv[ci] = __ldg(t + (size_t)(b*32+ci)*1024 + p);
  #pragma unroll 4
  for (int co=0;co<128;co++){
    float a = 0.f;
    const float* wr = &sw[co*32];
    #pragma unroll
    for (int ci=0;ci<32;ci++) a = fmaf(wr[ci], rv[ci], a);
    x[(size_t)(b*128+co)*1024 + p] += a;
  }
}

// ---------------- pre-quant 1x1: relu(in) -> z NHWC, smem weights ------------
__global__ void __launch_bounds__(256)
k_pqv(int in_id, const float* __restrict__ w, const float* __restrict__ bias)
{
  __shared__ float swT[128*64];
  const float* h = gbuf_c(in_id, nullptr);
  int b = blockIdx.y, p = blockIdx.x*256 + threadIdx.x;
  for (int i=threadIdx.x; i<8192; i+=256){
    int d = i >> 7, ci = i & 127;
    swT[ci*64 + d] = __ldg(w + i);
  }
  __syncthreads();
  float acc[64];
  #pragma unroll
  for (int d=0;d<64;d++) acc[d] = __ldg(bias+d);
  const float* ip = h + (size_t)b*128*1024 + p;
  for (int ci=0;ci<128;ci++){
    float v = fmaxf(__ldg(ip + (size_t)ci*1024), 0.f);
    const float4* wr = reinterpret_cast<const float4*>(&swT[ci*64]);
    #pragma unroll
    for (int q=0;q<16;q++){
      float4 wv = wr[q];
      acc[4*q  ]=fmaf(wv.x,v,acc[4*q  ]); acc[4*q+1]=fmaf(wv.y,v,acc[4*q+1]);
      acc[4*q+2]=fmaf(wv.z,v,acc[4*q+2]); acc[4*q+3]=fmaf(wv.w,v,acc[4*q+3]);
    }
  }
  float4* zp = reinterpret_cast<float4*>(g_Z + (size_t)(b*1024+p)*64);
  #pragma unroll
  for (int q=0;q<16;q++) zp[q] = make_float4(acc[4*q],acc[4*q+1],acc[4*q+2],acc[4*q+3]);
}

// ---------------- VQ: argmin, gather to NCHW, loss partials (unchanged) ------
__global__ void k_vq(const float* __restrict__ emb){
  __shared__ __align__(16) float sE[128*64];
  __shared__ float sQ[128];
  __shared__ double sred[128];
  int tid = threadIdx.x;
  int n = blockIdx.x*128 + tid;
  int b = n >> 10, p = n & 1023;
  float zr[64];
  {
    const float4* zp = reinterpret_cast<const float4*>(g_Z + (size_t)n*64);
    float4* zr4 = reinterpret_cast<float4*>(zr);
    #pragma unroll
    for (int i=0;i<16;i++) zr4[i] = zp[i];
  }
  float best = FLT_MAX; int bi = 0;
  for (int c=0;c<8;c++){
    const float4* src = reinterpret_cast<const float4*>(emb) + (size_t)c*2048;
    float4* dst = reinterpret_cast<float4*>(sE);
    #pragma unroll
    for (int r=0;r<16;r++) dst[tid + r*128] = src[tid + r*128];
    sQ[tid] = g_ESQ[c*128+tid];
    __syncthreads();
    for (int kk=0;kk<128;kk++){
      const float4* e = reinterpret_cast<const float4*>(sE + kk*64);
      float d0=0.f,d1=0.f,d2=0.f,d3=0.f;
      #pragma unroll
      for (int i=0;i<16;i++){
        float4 ev = e[i];
        float4 zv = reinterpret_cast<float4*>(zr)[i];
        d0 = fmaf(ev.x,zv.x,d0); d1 = fmaf(ev.y,zv.y,d1);
        d2 = fmaf(ev.z,zv.z,d2); d3 = fmaf(ev.w,zv.w,d3);
      }
      float sc = sQ[kk] - 2.f*((d0+d1)+(d2+d3));
      if (sc < best){ best = sc; bi = c*128+kk; }   // strict < : first min
    }
    __syncthreads();
  }
  g_IDX[n] = bi;
  const float* er = emb + (size_t)bi*64;
  float ls = 0.f;
  #pragma unroll
  for (int d=0; d<64; d++){
    float e = __ldg(er+d);
    g_ZQ[(size_t)(b*64+d)*1024 + p] = e;
    float df = e - zr[d];
    ls = fmaf(df,df,ls);
  }
  sred[tid] = (double)ls;
  __syncthreads();
  #pragma unroll
  for (int s=64;s>0;s>>=1){
    if (tid<s) sred[tid] += sred[tid+s];
    __syncthreads();
  }
  if (tid==0) g_PART[blockIdx.x] = sred[0];
}

// ---------------- ConvTranspose 4x4 s2 p1: 128@32 -> 64@64, f32x2 ------------
__global__ void __launch_bounds__(256,2)
k_convT2s(const float* __restrict__ bias)
{
  constexpr int CP = 8;  // 16 couts as 8 pairs
  __shared__ float sIn[2][10*40];
  int co0 = blockIdx.x*16;
  int yq0 = blockIdx.y*8;
  int b   = blockIdx.z;
  int tid = threadIdx.x;
  int tx = tid & 31, ty = tid >> 5;

  u64 acc[CP][4];
  #pragma unroll
  for (int j=0;j<CP;j++)
    #pragma unroll
    for (int q=0;q<4;q++) acc[j][q] = 0ull;

  const float* ipb = g_D1 + (size_t)b*128*1024;
  int r0 = tid/34, c0 = tid - r0*34;
  int r1 = (tid+256)/34, c1 = (tid+256) - r1*34;
  bool has1 = (tid+256) < 340;
  float s0, s1 = 0.f;
  {
    const float* ip = ipb;
    int giy = yq0-1+r0, gix = c0-1;
    s0 = (giy>=0&&giy<32&&gix>=0&&gix<32)?fmaxf(__ldg(ip+giy*32+gix),0.f):0.f;
    if (has1){
      int giy1 = yq0-1+r1, gix1 = c1-1;
      s1 = (giy1>=0&&giy1<32&&gix1>=0&&gix1<32)?fmaxf(__ldg(ip+giy1*32+gix1),0.f):0.f;
    }
  }
  int pb = 0;
  for (int ci=0; ci<128; ci++){
    sIn[pb][r0*40 + c0] = s0;
    if (has1) sIn[pb][r1*40 + c1] = s1;
    __syncthreads();
    if (ci+1 < 128){
      const float* ip = ipb + (size_t)(ci+1)*1024;
      int giy = yq0-1+r0, gix = c0-1;
      s0 = (giy>=0&&giy<32&&gix>=0&&gix<32)?fmaxf(__ldg(ip+giy*32+gix),0.f):0.f;
      if (has1){
        int giy1 = yq0-1+r1, gix1 = c1-1;
        s1 = (giy1>=0&&giy1<32&&gix1>=0&&gix1<32)?fmaxf(__ldg(ip+giy1*32+gix1),0.f):0.f;
      }
    }
    u64 rp[9];
    #pragma unroll
    for (int dy=0;dy<3;dy++)
      #pragma unroll
      for (int dx=0;dx<3;dx++){
        float rv = sIn[pb][(ty+dy)*40 + tx+dx];
        rp[dy*3+dx] = pk2(rv,rv);
      }
    const float* wp = g_TW_D2 + (size_t)ci*16*64 + co0;
    #pragma unroll
    for (int ky=0;ky<4;ky++){
      #pragma unroll
      for (int kx=0;kx<4;kx++){
        u64 rv = rp[((4-ky)>>1)*3 + ((4-kx)>>1)];
        const int pp = (((ky&1)^1)<<1) | ((kx&1)^1);
        const ulonglong2* wq = reinterpret_cast<const ulonglong2*>(wp + (ky*4+kx)*64);
        #pragma unroll
        for (int j2=0;j2<CP/2;j2++){
          ulonglong2 wv = __ldg(wq + j2);
          fma2(acc[2*j2  ][pp], wv.x, rv);
          fma2(acc[2*j2+1][pp], wv.y, rv);
        }
      }
    }
    pb ^= 1;
  }
  int yq = yq0 + ty;
  #pragma unroll
  for (int j=0;j<CP;j++){
    float2 f0=up2(acc[j][0]), f1=up2(acc[j][1]), f2=up2(acc[j][2]), f3=up2(acc[j][3]);
    float bvx = __ldg(bias+co0+2*j), bvy = __ldg(bias+co0+2*j+1);
    float* opx = g_U1 + (size_t)(b*64+co0+2*j)*4096;
    float* opy = g_U1 + (size_t)(b*64+co0+2*j+1)*4096;
    float2 ex0 = make_float2(fmaxf(f0.x+bvx,0.f), fmaxf(f1.x+bvx,0.f));
    float2 ex1 = make_float2(fmaxf(f2.x+bvx,0.f), fmaxf(f3.x+bvx,0.f));
    float2 ey0 = make_float2(fmaxf(f0.y+bvy,0.f), fmaxf(f1.y+bvy,0.f));
    float2 ey1 = make_float2(fmaxf(f2.y+bvy,0.f), fmaxf(f3.y+bvy,0.f));
    *reinterpret_cast<float2*>(opx + (2*yq+0)*64 + 2*tx) = ex0;
    *reinterpret_cast<float2*>(opx + (2*yq+1)*64 + 2*tx) = ex1;
    *reinterpret_cast<float2*>(opy + (2*yq+0)*64 + 2*tx) = ey0;
    *reinterpret_cast<float2*>(opy + (2*yq+1)*64 + 2*tx) = ey1;
  }
}

// ---------------- ConvTranspose 4x4 s2 p1: 64@64 -> 3@128 (recon) ------------
__global__ void __launch_bounds__(256,2)
k_convT3s(const float* __restrict__ bias, float* __restrict__ out)
{
  __shared__ float sIn[2][10*40];
  int xq0 = blockIdx.x*32;
  int yq0 = blockIdx.y*8;
  int b   = blockIdx.z;
  int tid = threadIdx.x;
  int tx = tid & 31, ty = tid >> 5;

  float acc[3][4];
  #pragma unroll
  for (int j=0;j<3;j++)
    #pragma unroll
    for (int q=0;q<4;q++) acc[j][q]=0.f;

  const float* ipb = g_U1 + (size_t)b*64*4096;
  int r0 = tid/34, c0 = tid - r0*34;
  int r1 = (tid+256)/34, c1 = (tid+256) - r1*34;
  bool has1 = (tid+256) < 340;
  float s0, s1 = 0.f;
  {
    int giy = yq0-1+r0, gix = xq0-1+c0;
    s0 = (giy>=0&&giy<64&&gix>=0&&gix<64)?__ldg(ipb+giy*64+gix):0.f;
    if (has1){
      int giy1 = yq0-1+r1, gix1 = xq0-1+c1;
      s1 = (giy1>=0&&giy1<64&&gix1>=0&&gix1<64)?__ldg(ipb+giy1*64+gix1):0.f;
    }
  }
  int pb = 0;
  for (int ci=0; ci<64; ci++){
    sIn[pb][r0*40 + c0] = s0;
    if (has1) sIn[pb][r1*40 + c1] = s1;
    __syncthreads();
    if (ci+1 < 64){
      const float* ip = ipb + (size_t)(ci+1)*4096;
      int giy = yq0-1+r0, gix = xq0-1+c0;
      s0 = (giy>=0&&giy<64&&gix>=0&&gix<64)?__ldg(ip+giy*64+gix):0.f;
      if (has1){
        int giy1 = yq0-1+r1, gix1 = xq0-1+c1;
        s1 = (giy1>=0&&giy1<64&&gix1>=0&&gix1<64)?__ldg(ip+giy1*64+gix1):0.f;
      }
    }
    float r3[3][3];
    #pragma unroll
    for (int dy=0;dy<3;dy++)
      #pragma unroll
      for (int dx=0;dx<3;dx++)
        r3[dy][dx] = sIn[pb][(ty+dy)*40 + tx+dx];
    const float* wp = g_TW_D3 + (size_t)ci*64;
    #pragma unroll
    for (int ky=0;ky<4;ky++){
      #pragma unroll
      for (int kx=0;kx<4;kx++){
        float rv = r3[(4-ky)>>1][(4-kx)>>1];
        const int pp = (((ky&1)^1)<<1) | ((kx&1)^1);
        float4 wv = __ldg(reinterpret_cast<const float4*>(wp + (ky*4+kx)*4));
        acc[0][pp]=fmaf(wv.x,rv,acc[0][pp]);
        acc[1][pp]=fmaf(wv.y,rv,acc[1][pp]);
        acc[2][pp]=fmaf(wv.z,rv,acc[2][pp]);
      }
    }
    pb ^= 1;
  }
  int yq = yq0 + ty, xq = xq0 + tx;
  #pragma unroll
  for (int j=0;j<3;j++){
    float bv = __ldg(bias+j);
    float* op = out + (size_t)(b*3+j)*16384;
    float2 e0 = make_float2(acc[j][0]+bv, acc[j][1]+bv);
    float2 e1 = make_float2(acc[j][2]+bv, acc[j][3]+bv);
    *reinterpret_cast<float2*>(op + (2*yq+0)*128 + 2*xq) = e0;
    *reinterpret_cast<float2*>(op + (2*yq+1)*128 + 2*xq) = e1;
  }
}

// ---------------- finalize: idx as float + deterministic loss ----------------
__global__ void k_final(float* __restrict__ out){
  int t = blockIdx.x*blockDim.x + threadIdx.x;
  if (t < 65536) out[3145730 + t] = (float)g_IDX[t];
  if (t == 0){
    double s = 0.0;
    for (int i=0;i<512;i++) s += g_PART[i];
    float m = (float)(s / 4194304.0);
    out[3145728] = m;   // codebook_loss
    out[3145729] = m;   // commitment_loss (identical value)
  }
}

// ---------------- launcher ---------------------------------------------------
extern "C" void kernel_launch(void* const* d_in, const int* in_sizes, int n_in,
                              void* d_out, int out_size)
{
  const float* patch=(const float*)d_in[0];
  const float* ew1=(const float*)d_in[1];  const float* eb1=(const float*)d_in[2];
  const float* ew2=(const float*)d_in[3];  const float* eb2=(const float*)d_in[4];
  const float* ew3=(const float*)d_in[5];  const float* eb3=(const float*)d_in[6];
  const float* er1a=(const float*)d_in[7]; const float* er1b=(const float*)d_in[8];
  const float* er2a=(const float*)d_in[9]; const float* er2b=(const float*)d_in[10];
  const float* pqw=(const float*)d_in[11]; const float* pqb=(const float*)d_in[12];
  const float* emb=(const float*)d_in[13];
  const float* dw1=(const float*)d_in[14]; const float* db1=(const float*)d_in[15];
  const float* dr1a=(const float*)d_in[16];const float* dr1b=(const float*)d_in[17];
  const float* dr2a=(const float*)d_in[18];const float* dr2b=(const float*)d_in[19];
  const float* dw2=(const float*)d_in[20]; const float* db2=(const float*)d_in[21];
  const float* dw3=(const float*)d_in[22]; const float* db3=(const float*)d_in[23];
  float* out = (float*)d_out;
  (void)in_sizes; (void)n_in; (void)out_size;

  // esq + all weight transposes in one kernel (637952 work items)
  k_prep<<<2492,256>>>(emb, ew1, ew2, ew3, er1a, er2a, dr1a, dr2a, dw1, dw2, dw3);

  // encoder
  k_conv4s<3,64,128,16> <<<dim3(4,4,NB),256>>>(patch, -1, 10, eb1, 0);
  k_conv4s<64,128,64,8> <<<dim3(16,1,NB),256>>>(nullptr, 0, 11, eb2, 1);
  k_conv3s<128,128,16,false,false,true><<<dim3(8,NB),256>>>(1, 12, eb3, 2);
  // residual block 1
  k_conv3s<128,32,8,true,true,false><<<dim3(4,NB),256>>>(2, 13, nullptr, 3);
  k_res1x1v<<<dim3(4,NB),256>>>(3, er1b, 2);
  // residual block 2
  k_conv3s<128,32,8,true,true,false><<<dim3(4,NB),256>>>(2, 14, nullptr, 3);
  k_res1x1v<<<dim3(4,NB),256>>>(3, er2b, 2);
  // pre-quant (relu fused into input)
  k_pqv<<<dim3(4,NB),256>>>(2, pqw, pqb);
  // vector quantization
  k_vq<<<512,128>>>(emb);

  // decoder
  k_conv3s<64,128,16,false,false,true><<<dim3(8,NB),256>>>(5, 17, db1, 6);
  k_conv3s<128,32,8,true,true,false><<<dim3(4,NB),256>>>(6, 15, nullptr, 3);
  k_res1x1v<<<dim3(4,NB),256>>>(3, dr1b, 6);
  k_conv3s<128,32,8,true,true,false><<<dim3(4,NB),256>>>(6, 16, nullptr, 3);
  k_res1x1v<<<dim3(4,NB),256>>>(3, dr2b, 6);
  k_convT2s<<<dim3(4,4,NB),256>>>(db2);
  k_convT3s<<<dim3(2,8,NB),256>>>(db3, out);

  // losses + indices
  k_final<<<256,256>>>(out);
}

// round 9
// speedup vs baseline: 1.7049x; 1.4497x over previous
#include <cuda_runtime.h>
#include <cfloat>
#include <cstddef>

#define NB 64   // batch

typedef unsigned long long u64;

// ---- packed f32x2 helpers ---------------------------------------------------
__device__ __forceinline__ u64 pk2(float lo, float hi){
  u64 r; asm("mov.b64 %0,{%1,%2};" : "=l"(r) : "f"(lo), "f"(hi)); return r;
}
__device__ __forceinline__ float2 up2(u64 v){
  float2 f; asm("mov.b64 {%0,%1},%2;" : "=f"(f.x), "=f"(f.y) : "l"(v)); return f;
}
__device__ __forceinline__ void fma2(u64 &d, u64 a, u64 b){
  asm("fma.rn.f32x2 %0,%1,%2,%0;" : "+l"(d) : "l"(a), "l"(b));
}

// ---------------- scratch buffers (device globals; no allocations) ----------
__device__ __align__(16) float g_A1[(size_t)NB*64*64*64];   // enc conv1 out
__device__ __align__(16) float g_A2[(size_t)NB*128*32*32];  // enc conv2 out
__device__ __align__(16) float g_A3[(size_t)NB*128*32*32];  // enc conv3/res
__device__ __align__(16) float g_T [(size_t)NB*32*32*32];   // res 3x3 temp
__device__ __align__(16) float g_Z [(size_t)NB*32*32*64];   // z NHWC
__device__ __align__(16) float g_ZQ[(size_t)NB*64*32*32];   // z_q NCHW
__device__ __align__(16) float g_D1[(size_t)NB*128*32*32];  // dec trunk
__device__ __align__(16) float g_U1[(size_t)NB*64*64*64];   // dec upsample
// pre-transposed weights: [ci][tap][co]
__device__ __align__(16) float g_TW_E1[3*16*64];
__device__ __align__(16) float g_TW_E2[64*16*128];
__device__ __align__(16) float g_TW_E3[128*9*128];
__device__ __align__(16) float g_TW_R1A[128*9*32];
__device__ __align__(16) float g_TW_R2A[128*9*32];
__device__ __align__(16) float g_TW_DR1A[128*9*32];
__device__ __align__(16) float g_TW_DR2A[128*9*32];
__device__ __align__(16) float g_TW_DEC[64*9*128];          // flipped dw1
__device__ __align__(16) float g_TW_D2[128*16*64];
__device__ __align__(16) float g_TW_D3[64*16*4];            // co padded 3->4
__device__ float  g_ESQ[1024];
__device__ int    g_IDX[65536];
__device__ double g_PART[512];

__device__ __forceinline__ float* gbuf(int id){
  switch(id){
    case 0: return g_A1; case 1: return g_A2; case 2: return g_A3;
    case 3: return g_T;  case 4: return g_Z;  case 5: return g_ZQ;
    case 6: return g_D1; case 7: return g_U1;
    case 10: return g_TW_E1;  case 11: return g_TW_E2;  case 12: return g_TW_E3;
    case 13: return g_TW_R1A; case 14: return g_TW_R2A; case 15: return g_TW_DR1A;
    case 16: return g_TW_DR2A;case 17: return g_TW_DEC; case 18: return g_TW_D2;
    default: return g_TW_D3;
  }
}
__device__ __forceinline__ const float* gbuf_c(int id, const float* ext){
  if (id < 0) return ext;
  return gbuf(id);
}

// ---------------- merged prep: esq + all weight transposes -------------------
__device__ __forceinline__ void trA_i(const float* __restrict__ w, float* T,
                                      int CI,int CO,int KK,int t){
  int co = t/(CI*KK); int r = t%(CI*KK); int ci = r/KK, kk = r%KK;
  T[((size_t)ci*KK+kk)*CO+co] = w[t];
}
__device__ __forceinline__ void trB_i(const float* __restrict__ w, float* T,
                                      int CI,int CO,int KK,int COP,int t){
  int ci = t/(CO*KK); int r = t%(CO*KK); int co = r/KK, kk = r%KK;
  T[((size_t)ci*KK+kk)*COP+co] = w[t];
}

__global__ void k_prep(const float* __restrict__ emb,
                       const float* __restrict__ ew1, const float* __restrict__ ew2,
                       const float* __restrict__ ew3,
                       const float* __restrict__ er1a, const float* __restrict__ er2a,
                       const float* __restrict__ dr1a, const float* __restrict__ dr2a,
                       const float* __restrict__ dw1, const float* __restrict__ dw2,
                       const float* __restrict__ dw3)
{
  int t = blockIdx.x*256 + threadIdx.x;
  if (t < 1024){
    const float4* e = reinterpret_cast<const float4*>(emb + (size_t)t*64);
    float s = 0.f;
    #pragma unroll
    for (int i=0;i<16;i++){
      float4 v = e[i];
      s = fmaf(v.x,v.x,fmaf(v.y,v.y,fmaf(v.z,v.z,fmaf(v.w,v.w,s))));
    }
    g_ESQ[t] = s; return;
  } t -= 1024;
  if (t < 3072){ trA_i(ew1, g_TW_E1, 3,64,16, t); return; } t -= 3072;
  if (t < 131072){ trA_i(ew2, g_TW_E2, 64,128,16, t); return; } t -= 131072;
  if (t < 147456){ trA_i(ew3, g_TW_E3, 128,128,9, t); return; } t -= 147456;
  if (t < 36864){ trA_i(er1a, g_TW_R1A, 128,32,9, t); return; } t -= 36864;
  if (t < 36864){ trA_i(er2a, g_TW_R2A, 128,32,9, t); return; } t -= 36864;
  if (t < 36864){ trA_i(dr1a, g_TW_DR1A, 128,32,9, t); return; } t -= 36864;
  if (t < 36864){ trA_i(dr2a, g_TW_DR2A, 128,32,9, t); return; } t -= 36864;
  if (t < 73728){
    int ci = t/(128*9); int r = t%(128*9); int co = r/9, kk = r%9;
    int ky = kk/3, kx = kk%3;
    g_TW_DEC[((size_t)ci*9 + (2-ky)*3 + (2-kx))*128 + co] = dw1[t]; return;
  } t -= 73728;
  if (t < 131072){ trB_i(dw2, g_TW_D2, 128,64,16,64, t); return; } t -= 131072;
  if (t < 3072){ trB_i(dw3, g_TW_D3, 64,3,16,4, t); }
}

// ---------------- 3x3 s1 p1 conv at 32x32, f32x2, dbl-buf input+weights ------
template<int CIN,int COUT,int COT,bool RIN,bool ROUT,bool HASB>
__global__ void __launch_bounds__(256,2)
k_conv3s(int in_id, int w_id, const float* __restrict__ bias, int out_id)
{
  constexpr int CP  = COT/2;
  constexpr int WSZ = 9*COT;          // weight floats per ci for this block
  __shared__ __align__(16) float sIn[2][34*40];
  __shared__ __align__(16) float sW [2][WSZ];
  const float* in = gbuf_c(in_id, nullptr);
  const float* W  = gbuf_c(w_id, nullptr);
  float* out = gbuf(out_id);
  int co0 = blockIdx.x*COT;
  int b   = blockIdx.y;
  int tid = threadIdx.x;
  int tx = tid & 7, ty = tid >> 3;
  int x0 = tx*4;

  for (int i=tid; i<34*40; i+=256){ sIn[0][i]=0.f; sIn[1][i]=0.f; }
  __syncthreads();

  u64 acc[CP][4];
  #pragma unroll
  for (int j=0;j<CP;j++){
    u64 bp = HASB ? pk2(__ldg(bias+co0+2*j), __ldg(bias+co0+2*j+1)) : 0ull;
    #pragma unroll
    for (int p=0;p<4;p++) acc[j][p] = bp;
  }

  const float* ipb = in + (size_t)b*CIN*1024;
  // weight element this thread stages each iteration
  int wk = tid / COT, wj = tid % COT;       // tap, co
  bool wact = tid < WSZ;
  const float* wsrc0 = W + (size_t)wk*COUT + co0 + wj;

  float4 v4 = __ldg(reinterpret_cast<const float4*>(ipb) + tid);
  if (RIN){ v4.x=fmaxf(v4.x,0.f); v4.y=fmaxf(v4.y,0.f); v4.z=fmaxf(v4.z,0.f); v4.w=fmaxf(v4.w,0.f); }
  float wv0 = wact ? __ldg(wsrc0) : 0.f;

  int pb = 0;
  for (int ci=0; ci<CIN; ci++){
    float* sp = &sIn[pb][(ty+1)*40 + 1 + x0];
    sp[0]=v4.x; sp[1]=v4.y; sp[2]=v4.z; sp[3]=v4.w;
    if (wact) sW[pb][tid] = wv0;
    __syncthreads();
    if (ci+1 < CIN){
      v4 = __ldg(reinterpret_cast<const float4*>(ipb + (size_t)(ci+1)*1024) + tid);
      if (RIN){ v4.x=fmaxf(v4.x,0.f); v4.y=fmaxf(v4.y,0.f); v4.z=fmaxf(v4.z,0.f); v4.w=fmaxf(v4.w,0.f); }
      if (wact) wv0 = __ldg(wsrc0 + (size_t)(ci+1)*9*COUT);
    }
    #pragma unroll
    for (int ky=0;ky<3;ky++){
      const float* row = &sIn[pb][(ty+ky)*40 + x0];
      float4 a = *reinterpret_cast<const float4*>(row);
      float e4 = row[4], e5 = row[5];
      u64 vb[6];
      vb[0]=pk2(a.x,a.x); vb[1]=pk2(a.y,a.y); vb[2]=pk2(a.z,a.z);
      vb[3]=pk2(a.w,a.w); vb[4]=pk2(e4,e4);  vb[5]=pk2(e5,e5);
      #pragma unroll
      for (int kx=0;kx<3;kx++){
        const ulonglong2* wq = reinterpret_cast<const ulonglong2*>(&sW[pb][(ky*3+kx)*COT]);
        #pragma unroll
        for (int j2=0;j2<CP/2;j2++){
          ulonglong2 wv = wq[j2];
          #pragma unroll
          for (int p=0;p<4;p++){
            fma2(acc[2*j2  ][p], wv.x, vb[kx+p]);
            fma2(acc[2*j2+1][p], wv.y, vb[kx+p]);
          }
        }
      }
    }
    pb ^= 1;
  }
  #pragma unroll
  for (int j=0;j<CP;j++){
    float2 f0=up2(acc[j][0]), f1=up2(acc[j][1]), f2=up2(acc[j][2]), f3=up2(acc[j][3]);
    float4 oe = make_float4(f0.x,f1.x,f2.x,f3.x);
    float4 oo = make_float4(f0.y,f1.y,f2.y,f3.y);
    if (ROUT){
      oe.x=fmaxf(oe.x,0.f); oe.y=fmaxf(oe.y,0.f); oe.z=fmaxf(oe.z,0.f); oe.w=fmaxf(oe.w,0.f);
      oo.x=fmaxf(oo.x,0.f); oo.y=fmaxf(oo.y,0.f); oo.z=fmaxf(oo.z,0.f); oo.w=fmaxf(oo.w,0.f);
    }
    *reinterpret_cast<float4*>(out + ((size_t)(b*COUT+co0+2*j  )*32 + ty)*32 + x0) = oe;
    *reinterpret_cast<float4*>(out + ((size_t)(b*COUT+co0+2*j+1)*32 + ty)*32 + x0) = oo;
  }
}

// ---------------- 4x4 s2 p1 conv, f32x2, dbl-buf input+weights ---------------
template<int CIN,int COUT,int HIN,int COT>
__global__ void __launch_bounds__(256,2)
k_conv4s(const float* __restrict__ ext_in, int in_id, int w_id,
         const float* __restrict__ bias, int out_id)
{
  constexpr int CP = COT/2;
  constexpr int HOUT = HIN/2;
  constexpr int XT   = HOUT/32;
  constexpr int WSZ  = 16*COT;
  __shared__ __align__(16) float sIn[2][66*72];
  __shared__ __align__(16) float sW [2][WSZ];
  const float* in = gbuf_c(in_id, ext_in);
  const float* W  = gbuf_c(w_id, nullptr);
  float* out = gbuf(out_id);
  int co0 = blockIdx.x*COT;
  int oy0 = (blockIdx.y/XT)*32, ox0 = (blockIdx.y%XT)*32;
  int b = blockIdx.z;
  int tid = threadIdx.x;
  int tx = tid & 7, ty = tid >> 3;
  int x0 = tx*4;

  u64 acc[CP][4];
  #pragma unroll
  for (int j=0;j<CP;j++){
    u64 bp = pk2(__ldg(bias+co0+2*j), __ldg(bias+co0+2*j+1));
    #pragma unroll
    for (int p=0;p<4;p++) acc[j][p] = bp;
  }

  int iy0 = oy0*2 - 1, ix0 = ox0*2 - 1;
  int wk = tid / COT, wj = tid % COT;
  bool wact = tid < WSZ;
  const float* wsrc0 = W + (size_t)wk*COUT + co0 + wj;

  float sreg[18];
  {
    const float* ip = in + (size_t)b*CIN*HIN*HIN;
    #pragma unroll
    for (int t=0;t<18;t++){
      int s = tid + t*256; float v = 0.f;
      if (s < 4356){
        int r = s/66, c = s - r*66;
        int giy = iy0 + r, gix = ix0 + c;
        if (giy>=0 && giy<HIN && gix>=0 && gix<HIN) v = __ldg(ip + (size_t)giy*HIN + gix);
      }
      sreg[t] = v;
    }
  }
  float wv0 = wact ? __ldg(wsrc0) : 0.f;

  int pb = 0;
  for (int ci=0; ci<CIN; ci++){
    #pragma unroll
    for (int t=0;t<18;t++){
      int s = tid + t*256;
      if (s < 4356){ int r = s/66, c = s - r*66; sIn[pb][r*72 + c] = sreg[t]; }
    }
    if (wact) sW[pb][tid] = wv0;
    __syncthreads();
    if (ci+1 < CIN){
      const float* ip = in + (size_t)(b*CIN+ci+1)*HIN*HIN;
      #pragma unroll
      for (int t=0;t<18;t++){
        int s = tid + t*256; float v = 0.f;
        if (s < 4356){
          int r = s/66, c = s - r*66;
          int giy = iy0 + r, gix = ix0 + c;
          if (giy>=0 && giy<HIN && gix>=0 && gix<HIN) v = __ldg(ip + (size_t)giy*HIN + gix);
        }
        sreg[t] = v;
      }
      if (wact) wv0 = __ldg(wsrc0 + (size_t)(ci+1)*16*COUT);
    }
    #pragma unroll
    for (int ky=0;ky<4;ky++){
      const float* row = &sIn[pb][(2*ty+ky)*72 + 2*x0];
      float4 a  = *reinterpret_cast<const float4*>(row);
      float4 bq = *reinterpret_cast<const float4*>(row+4);
      float e8 = row[8], e9 = row[9];
      u64 vb[10];
      vb[0]=pk2(a.x,a.x); vb[1]=pk2(a.y,a.y); vb[2]=pk2(a.z,a.z); vb[3]=pk2(a.w,a.w);
      vb[4]=pk2(bq.x,bq.x); vb[5]=pk2(bq.y,bq.y); vb[6]=pk2(bq.z,bq.z); vb[7]=pk2(bq.w,bq.w);
      vb[8]=pk2(e8,e8); vb[9]=pk2(e9,e9);
      #pragma unroll
      for (int kx=0;kx<4;kx++){
        const ulonglong2* wq = reinterpret_cast<const ulonglong2*>(&sW[pb][(ky*4+kx)*COT]);
        #pragma unroll
        for (int j2=0;j2<CP/2;j2++){
          ulonglong2 wv = wq[j2];
          #pragma unroll
          for (int p=0;p<4;p++){
            fma2(acc[2*j2  ][p], wv.x, vb[kx+2*p]);
            fma2(acc[2*j2+1][p], wv.y, vb[kx+2*p]);
          }
        }
      }
    }
    pb ^= 1;
  }
  #pragma unroll
  for (int j=0;j<CP;j++){
    float2 f0=up2(acc[j][0]), f1=up2(acc[j][1]), f2=up2(acc[j][2]), f3=up2(acc[j][3]);
    float4 oe = make_float4(fmaxf(f0.x,0.f),fmaxf(f1.x,0.f),fmaxf(f2.x,0.f),fmaxf(f3.x,0.f));
    float4 oo = make_float4(fmaxf(f0.y,0.f),fmaxf(f1.y,0.f),fmaxf(f2.y,0.f),fmaxf(f3.y,0.f));
    *reinterpret_cast<float4*>(out + ((size_t)(b*COUT+co0+2*j  )*HOUT + oy0+ty)*HOUT + ox0+x0) = oe;
    *reinterpret_cast<float4*>(out + ((size_t)(b*COUT+co0+2*j+1)*HOUT + oy0+ty)*HOUT + ox0+x0) = oo;
  }
}

// ---------------- 1x1 conv residual-add, smem weights, input read once -------
__global__ void __launch_bounds__(256)
k_res1x1v(int t_id, const float* __restrict__ w, int x_id)
{
  __shared__ float sw[128*32];
  const float* t = gbuf_c(t_id, nullptr);
  float* x = gbuf(x_id);
  int b = blockIdx.y, p = blockIdx.x*256 + threadIdx.x;
  for (int i=threadIdx.x; i<4096; i+=256) sw[i] = __ldg(w+i);
  __syncthreads();
  float rv[32];
  #pragma unroll
  for (int ci=0;ci<32;ci++) rv[ci] = __ldg(t + (size_t)(b*32+ci)*1024 + p);
  #pragma unroll 4
  for (int co=0;co<128;co++){
    float a = 0.f;
    const float* wr = &sw[co*32];
    #pragma unroll
    for (int ci=0;ci<32;ci++) a = fmaf(wr[ci], rv[ci], a);
    x[(size_t)(b*128+co)*1024 + p] += a;
  }
}

// ---------------- pre-quant 1x1: relu(in) -> z NHWC, smem weights ------------
__global__ void __launch_bounds__(256)
k_pqv(int in_id, const float* __restrict__ w, const float* __restrict__ bias)
{
  __shared__ float swT[128*64];
  const float* h = gbuf_c(in_id, nullptr);
  int b = blockIdx.y, p = blockIdx.x*256 + threadIdx.x;
  for (int i=threadIdx.x; i<8192; i+=256){
    int d = i >> 7, ci = i & 127;
    swT[ci*64 + d] = __ldg(w + i);
  }
  __syncthreads();
  float acc[64];
  #pragma unroll
  for (int d=0;d<64;d++) acc[d] = __ldg(bias+d);
  const float* ip = h + (size_t)b*128*1024 + p;
  for (int ci=0;ci<128;ci++){
    float v = fmaxf(__ldg(ip + (size_t)ci*1024), 0.f);
    const float4* wr = reinterpret_cast<const float4*>(&swT[ci*64]);
    #pragma unroll
    for (int q=0;q<16;q++){
      float4 wv = wr[q];
      acc[4*q  ]=fmaf(wv.x,v,acc[4*q  ]); acc[4*q+1]=fmaf(wv.y,v,acc[4*q+1]);
      acc[4*q+2]=fmaf(wv.z,v,acc[4*q+2]); acc[4*q+3]=fmaf(wv.w,v,acc[4*q+3]);
    }
  }
  float4* zp = reinterpret_cast<float4*>(g_Z + (size_t)(b*1024+p)*64);
  #pragma unroll
  for (int q=0;q<16;q++) zp[q] = make_float4(acc[4*q],acc[4*q+1],acc[4*q+2],acc[4*q+3]);
}

// ---------------- VQ: argmin, gather to NCHW, loss partials ------------------
__global__ void k_vq(const float* __restrict__ emb){
  __shared__ __align__(16) float sE[128*64];
  __shared__ float sQ[128];
  __shared__ double sred[128];
  int tid = threadIdx.x;
  int n = blockIdx.x*128 + tid;
  int b = n >> 10, p = n & 1023;
  float zr[64];
  {
    const float4* zp = reinterpret_cast<const float4*>(g_Z + (size_t)n*64);
    float4* zr4 = reinterpret_cast<float4*>(zr);
    #pragma unroll
    for (int i=0;i<16;i++) zr4[i] = zp[i];
  }
  float best = FLT_MAX; int bi = 0;
  for (int c=0;c<8;c++){
    const float4* src = reinterpret_cast<const float4*>(emb) + (size_t)c*2048;
    float4* dst = reinterpret_cast<float4*>(sE);
    #pragma unroll
    for (int r=0;r<16;r++) dst[tid + r*128] = src[tid + r*128];
    sQ[tid] = g_ESQ[c*128+tid];
    __syncthreads();
    for (int kk=0;kk<128;kk++){
      const float4* e = reinterpret_cast<const float4*>(sE + kk*64);
      float d0=0.f,d1=0.f,d2=0.f,d3=0.f;
      #pragma unroll
      for (int i=0;i<16;i++){
        float4 ev = e[i];
        float4 zv = reinterpret_cast<float4*>(zr)[i];
        d0 = fmaf(ev.x,zv.x,d0); d1 = fmaf(ev.y,zv.y,d1);
        d2 = fmaf(ev.z,zv.z,d2); d3 = fmaf(ev.w,zv.w,d3);
      }
      float sc = sQ[kk] - 2.f*((d0+d1)+(d2+d3));
      if (sc < best){ best = sc; bi = c*128+kk; }   // strict < : first min
    }
    __syncthreads();
  }
  g_IDX[n] = bi;
  const float* er = emb + (size_t)bi*64;
  float ls = 0.f;
  #pragma unroll
  for (int d=0; d<64; d++){
    float e = __ldg(er+d);
    g_ZQ[(size_t)(b*64+d)*1024 + p] = e;
    float df = e - zr[d];
    ls = fmaf(df,df,ls);
  }
  sred[tid] = (double)ls;
  __syncthreads();
  #pragma unroll
  for (int s=64;s>0;s>>=1){
    if (tid<s) sred[tid] += sred[tid+s];
    __syncthreads();
  }
  if (tid==0) g_PART[blockIdx.x] = sred[0];
}

// ---------------- ConvTranspose 4x4 s2 p1: 128@32 -> 64@64, f32x2 ------------
__global__ void __launch_bounds__(256,2)
k_convT2s(const float* __restrict__ bias)
{
  constexpr int CP = 8;  // 16 couts as 8 pairs
  __shared__ __align__(16) float sIn[2][10*40];
  __shared__ __align__(16) float sW [2][256];
  int co0 = blockIdx.x*16;
  int yq0 = blockIdx.y*8;
  int b   = blockIdx.z;
  int tid = threadIdx.x;
  int tx = tid & 31, ty = tid >> 5;

  u64 acc[CP][4];
  #pragma unroll
  for (int j=0;j<CP;j++)
    #pragma unroll
    for (int q=0;q<4;q++) acc[j][q] = 0ull;

  const float* ipb = g_D1 + (size_t)b*128*1024;
  int r0 = tid/34, c0 = tid - r0*34;
  int r1 = (tid+256)/34, c1 = (tid+256) - r1*34;
  bool has1 = (tid+256) < 340;
  int wk = tid >> 4, wj = tid & 15;                 // tap, co
  const float* wsrc0 = g_TW_D2 + (size_t)wk*64 + co0 + wj;
  float s0, s1 = 0.f;
  {
    const float* ip = ipb;
    int giy = yq0-1+r0, gix = c0-1;
    s0 = (giy>=0&&giy<32&&gix>=0&&gix<32)?fmaxf(__ldg(ip+giy*32+gix),0.f):0.f;
    if (has1){
      int giy1 = yq0-1+r1, gix1 = c1-1;
      s1 = (giy1>=0&&giy1<32&&gix1>=0&&gix1<32)?fmaxf(__ldg(ip+giy1*32+gix1),0.f):0.f;
    }
  }
  float wv0 = __ldg(wsrc0);
  int pb = 0;
  for (int ci=0; ci<128; ci++){
    sIn[pb][r0*40 + c0] = s0;
    if (has1) sIn[pb][r1*40 + c1] = s1;
    sW[pb][wk*16 + wj] = wv0;
    __syncthreads();
    if (ci+1 < 128){
      const float* ip = ipb + (size_t)(ci+1)*1024;
      int giy = yq0-1+r0, gix = c0-1;
      s0 = (giy>=0&&giy<32&&gix>=0&&gix<32)?fmaxf(__ldg(ip+giy*32+gix),0.f):0.f;
      if (has1){
        int giy1 = yq0-1+r1, gix1 = c1-1;
        s1 = (giy1>=0&&giy1<32&&gix1>=0&&gix1<32)?fmaxf(__ldg(ip+giy1*32+gix1),0.f):0.f;
      }
      wv0 = __ldg(wsrc0 + (size_t)(ci+1)*16*64);
    }
    u64 rp[9];
    #pragma unroll
    for (int dy=0;dy<3;dy++)
      #pragma unroll
      for (int dx=0;dx<3;dx++){
        float rv = sIn[pb][(ty+dy)*40 + tx+dx];
        rp[dy*3+dx] = pk2(rv,rv);
      }
    #pragma unroll
    for (int ky=0;ky<4;ky++){
      #pragma unroll
      for (int kx=0;kx<4;kx++){
        u64 rv = rp[((4-ky)>>1)*3 + ((4-kx)>>1)];
        const int pp = (((ky&1)^1)<<1) | ((kx&1)^1);
        const ulonglong2* wq = reinterpret_cast<const ulonglong2*>(&sW[pb][(ky*4+kx)*16]);
        #pragma unroll
        for (int j2=0;j2<CP/2;j2++){
          ulonglong2 wv = wq[j2];
          fma2(acc[2*j2  ][pp], wv.x, rv);
          fma2(acc[2*j2+1][pp], wv.y, rv);
        }
      }
    }
    pb ^= 1;
  }
  int yq = yq0 + ty;
  #pragma unroll
  for (int j=0;j<CP;j++){
    float2 f0=up2(acc[j][0]), f1=up2(acc[j][1]), f2=up2(acc[j][2]), f3=up2(acc[j][3]);
    float bvx = __ldg(bias+co0+2*j), bvy = __ldg(bias+co0+2*j+1);
    float* opx = g_U1 + (size_t)(b*64+co0+2*j)*4096;
    float* opy = g_U1 + (size_t)(b*64+co0+2*j+1)*4096;
    float2 ex0 = make_float2(fmaxf(f0.x+bvx,0.f), fmaxf(f1.x+bvx,0.f));
    float2 ex1 = make_float2(fmaxf(f2.x+bvx,0.f), fmaxf(f3.x+bvx,0.f));
    float2 ey0 = make_float2(fmaxf(f0.y+bvy,0.f), fmaxf(f1.y+bvy,0.f));
    float2 ey1 = make_float2(fmaxf(f2.y+bvy,0.f), fmaxf(f3.y+bvy,0.f));
    *reinterpret_cast<float2*>(opx + (2*yq+0)*64 + 2*tx) = ex0;
    *reinterpret_cast<float2*>(opx + (2*yq+1)*64 + 2*tx) = ex1;
    *reinterpret_cast<float2*>(opy + (2*yq+0)*64 + 2*tx) = ey0;
    *reinterpret_cast<float2*>(opy + (2*yq+1)*64 + 2*tx) = ey1;
  }
}

// ---------------- ConvTranspose 4x4 s2 p1: 64@64 -> 3@128 (recon) ------------
__global__ void __launch_bounds__(256,2)
k_convT3s(const float* __restrict__ bias, float* __restrict__ out)
{
  __shared__ __align__(16) float sIn[2][10*40];
  __shared__ __align__(16) float sW [2][64];
  int xq0 = blockIdx.x*32;
  int yq0 = blockIdx.y*8;
  int b   = blockIdx.z;
  int tid = threadIdx.x;
  int tx = tid & 31, ty = tid >> 5;

  float acc[3][4];
  #pragma unroll
  for (int j=0;j<3;j++)
    #pragma unroll
    for (int q=0;q<4;q++) acc[j][q]=0.f;

  const float* ipb = g_U1 + (size_t)b*64*4096;
  int r0 = tid/34, c0 = tid - r0*34;
  int r1 = (tid+256)/34, c1 = (tid+256) - r1*34;
  bool has1 = (tid+256) < 340;
  bool wact = tid < 64;
  float s0, s1 = 0.f;
  {
    int giy = yq0-1+r0, gix = xq0-1+c0;
    s0 = (giy>=0&&giy<64&&gix>=0&&gix<64)?__ldg(ipb+giy*64+gix):0.f;
    if (has1){
      int giy1 = yq0-1+r1, gix1 = xq0-1+c1;
      s1 = (giy1>=0&&giy1<64&&gix1>=0&&gix1<64)?__ldg(ipb+giy1*64+gix1):0.f;
    }
  }
  float wv0 = wact ? __ldg(g_TW_D3 + tid) : 0.f;
  int pb = 0;
  for (int ci=0; ci<64; ci++){
    sIn[pb][r0*40 + c0] = s0;
    if (has1) sIn[pb][r1*40 + c1] = s1;
    if (wact) sW[pb][tid] = wv0;
    __syncthreads();
    if (ci+1 < 64){
      const float* ip = ipb + (size_t)(ci+1)*4096;
      int giy = yq0-1+r0, gix = xq0-1+c0;
      s0 = (giy>=0&&giy<64&&gix>=0&&gix<64)?__ldg(ip+giy*64+gix):0.f;
      if (has1){
        int giy1 = yq0-1+r1, gix1 = xq0-1+c1;
        s1 = (giy1>=0&&giy1<64&&gix1>=0&&gix1<64)?__ldg(ip+giy1*64+gix1):0.f;
      }
      if (wact) wv0 = __ldg(g_TW_D3 + (size_t)(ci+1)*64 + tid);
    }
    float r3[3][3];
    #pragma unroll
    for (int dy=0;dy<3;dy++)
      #pragma unroll
      for (int dx=0;dx<3;dx++)
        r3[dy][dx] = sIn[pb][(ty+dy)*40 + tx+dx];
    #pragma unroll
    for (int ky=0;ky<4;ky++){
      #pragma unroll
      for (int kx=0;kx<4;kx++){
        float rv = r3[(4-ky)>>1][(4-kx)>>1];
        const int pp = (((ky&1)^1)<<1) | ((kx&1)^1);
        float4 wv = *reinterpret_cast<const float4*>(&sW[pb][(ky*4+kx)*4]);
        acc[0][pp]=fmaf(wv.x,rv,acc[0][pp]);
        acc[1][pp]=fmaf(wv.y,rv,acc[1][pp]);
        acc[2][pp]=fmaf(wv.z,rv,acc[2][pp]);
      }
    }
    pb ^= 1;
  }
  int yq = yq0 + ty, xq = xq0 + tx;
  #pragma unroll
  for (int j=0;j<3;j++){
    float bv = __ldg(bias+j);
    float* op = out + (size_t)(b*3+j)*16384;
    float2 e0 = make_float2(acc[j][0]+bv, acc[j][1]+bv);
    float2 e1 = make_float2(acc[j][2]+bv, acc[j][3]+bv);
    *reinterpret_cast<float2*>(op + (2*yq+0)*128 + 2*xq) = e0;
    *reinterpret_cast<float2*>(op + (2*yq+1)*128 + 2*xq) = e1;
  }
}

// ---------------- finalize: idx as float + deterministic loss ----------------
__global__ void k_final(float* __restrict__ out){
  int t = blockIdx.x*blockDim.x + threadIdx.x;
  if (t < 65536) out[3145730 + t] = (float)g_IDX[t];
  if (t == 0){
    double s = 0.0;
    for (int i=0;i<512;i++) s += g_PART[i];
    float m = (float)(s / 4194304.0);
    out[3145728] = m;   // codebook_loss
    out[3145729] = m;   // commitment_loss (identical value)
  }
}

// ---------------- launcher ---------------------------------------------------
extern "C" void kernel_launch(void* const* d_in, const int* in_sizes, int n_in,
                              void* d_out, int out_size)
{
  const float* patch=(const float*)d_in[0];
  const float* ew1=(const float*)d_in[1];  const float* eb1=(const float*)d_in[2];
  const float* ew2=(const float*)d_in[3];  const float* eb2=(const float*)d_in[4];
  const float* ew3=(const float*)d_in[5];  const float* eb3=(const float*)d_in[6];
  const float* er1a=(const float*)d_in[7]; const float* er1b=(const float*)d_in[8];
  const float* er2a=(const float*)d_in[9]; const float* er2b=(const float*)d_in[10];
  const float* pqw=(const float*)d_in[11]; const float* pqb=(const float*)d_in[12];
  const float* emb=(const float*)d_in[13];
  const float* dw1=(const float*)d_in[14]; const float* db1=(const float*)d_in[15];
  const float* dr1a=(const float*)d_in[16];const float* dr1b=(const float*)d_in[17];
  const float* dr2a=(const float*)d_in[18];const float* dr2b=(const float*)d_in[19];
  const float* dw2=(const float*)d_in[20]; const float* db2=(const float*)d_in[21];
  const float* dw3=(const float*)d_in[22]; const float* db3=(const float*)d_in[23];
  float* out = (float*)d_out;
  (void)in_sizes; (void)n_in; (void)out_size;

  // esq + all weight transposes in one kernel
  k_prep<<<2492,256>>>(emb, ew1, ew2, ew3, er1a, er2a, dr1a, dr2a, dw1, dw2, dw3);

  // encoder
  k_conv4s<3,64,128,16> <<<dim3(4,4,NB),256>>>(patch, -1, 10, eb1, 0);
  k_conv4s<64,128,64,8> <<<dim3(16,1,NB),256>>>(nullptr, 0, 11, eb2, 1);
  k_conv3s<128,128,16,false,false,true><<<dim3(8,NB),256>>>(1, 12, eb3, 2);
  // residual block 1
  k_conv3s<128,32,8,true,true,false><<<dim3(4,NB),256>>>(2, 13, nullptr, 3);
  k_res1x1v<<<dim3(4,NB),256>>>(3, er1b, 2);
  // residual block 2
  k_conv3s<128,32,8,true,true,false><<<dim3(4,NB),256>>>(2, 14, nullptr, 3);
  k_res1x1v<<<dim3(4,NB),256>>>(3, er2b, 2);
  // pre-quant (relu fused into input)
  k_pqv<<<dim3(4,NB),256>>>(2, pqw, pqb);
  // vector quantization
  k_vq<<<512,128>>>(emb);

  // decoder
  k_conv3s<64,128,16,false,false,true><<<dim3(8,NB),256>>>(5, 17, db1, 6);
  k_conv3s<128,32,8,true,true,false><<<dim3(4,NB),256>>>(6, 15, nullptr, 3);
  k_res1x1v<<<dim3(4,NB),256>>>(3, dr1b, 6);
  k_conv3s<128,32,8,true,true,false><<<dim3(4,NB),256>>>(6, 16, nullptr, 3);
  k_res1x1v<<<dim3(4,NB),256>>>(3, dr2b, 6);
  k_convT2s<<<dim3(4,4,NB),256>>>(db2);
  k_convT3s<<<dim3(2,8,NB),256>>>(db3, out);

  // losses + indices
  k_final<<<256,256>>>(out);
}

// round 10
// speedup vs baseline: 1.8165x; 1.0655x over previous
#include <cuda_runtime.h>
#include <cfloat>
#include <cstddef>

#define NB 64   // batch

typedef unsigned long long u64;

// ---- packed f32x2 helpers ---------------------------------------------------
__device__ __forceinline__ u64 pk2(float lo, float hi){
  u64 r; asm("mov.b64 %0,{%1,%2};" : "=l"(r) : "f"(lo), "f"(hi)); return r;
}
__device__ __forceinline__ float2 up2(u64 v){
  float2 f; asm("mov.b64 {%0,%1},%2;" : "=f"(f.x), "=f"(f.y) : "l"(v)); return f;
}
__device__ __forceinline__ void fma2(u64 &d, u64 a, u64 b){
  asm("fma.rn.f32x2 %0,%1,%2,%0;" : "+l"(d) : "l"(a), "l"(b));
}

// ---------------- scratch buffers (device globals; no allocations) ----------
__device__ __align__(16) float g_A1[(size_t)NB*64*64*64];   // enc conv1 out
__device__ __align__(16) float g_A2[(size_t)NB*128*32*32];  // enc conv2 out
__device__ __align__(16) float g_A3[(size_t)NB*128*32*32];  // enc conv3/res
__device__ __align__(16) float g_T [(size_t)NB*32*32*32];   // res 3x3 temp
__device__ __align__(16) float g_Z [(size_t)NB*32*32*64];   // z NHWC
__device__ __align__(16) float g_ZQ[(size_t)NB*64*32*32];   // z_q NCHW
__device__ __align__(16) float g_D1[(size_t)NB*128*32*32];  // dec trunk
__device__ __align__(16) float g_U1[(size_t)NB*64*64*64];   // dec upsample
// pre-transposed weights: [ci][tap][co]
__device__ __align__(16) float g_TW_E1[3*16*64];
__device__ __align__(16) float g_TW_E2[64*16*128];
__device__ __align__(16) float g_TW_E3[128*9*128];
__device__ __align__(16) float g_TW_R1A[128*9*32];
__device__ __align__(16) float g_TW_R2A[128*9*32];
__device__ __align__(16) float g_TW_DR1A[128*9*32];
__device__ __align__(16) float g_TW_DR2A[128*9*32];
__device__ __align__(16) float g_TW_DEC[64*9*128];          // flipped dw1
__device__ __align__(16) float g_TW_D2[128*16*64];
__device__ __align__(16) float g_TW_D3[64*16*4];            // co padded 3->4
__device__ float  g_ESQ[1024];
__device__ int    g_IDX[65536];
__device__ double g_PART[512];

__device__ __forceinline__ float* gbuf(int id){
  switch(id){
    case 0: return g_A1; case 1: return g_A2; case 2: return g_A3;
    case 3: return g_T;  case 4: return g_Z;  case 5: return g_ZQ;
    case 6: return g_D1; case 7: return g_U1;
    case 10: return g_TW_E1;  case 11: return g_TW_E2;  case 12: return g_TW_E3;
    case 13: return g_TW_R1A; case 14: return g_TW_R2A; case 15: return g_TW_DR1A;
    case 16: return g_TW_DR2A;case 17: return g_TW_DEC; case 18: return g_TW_D2;
    default: return g_TW_D3;
  }
}
__device__ __forceinline__ const float* gbuf_c(int id, const float* ext){
  if (id < 0) return ext;
  return gbuf(id);
}

// ---------------- merged prep: esq + all weight transposes -------------------
__device__ __forceinline__ void trA_i(const float* __restrict__ w, float* T,
                                      int CI,int CO,int KK,int t){
  int co = t/(CI*KK); int r = t%(CI*KK); int ci = r/KK, kk = r%KK;
  T[((size_t)ci*KK+kk)*CO+co] = w[t];
}
__device__ __forceinline__ void trB_i(const float* __restrict__ w, float* T,
                                      int CI,int CO,int KK,int COP,int t){
  int ci = t/(CO*KK); int r = t%(CO*KK); int co = r/KK, kk = r%KK;
  T[((size_t)ci*KK+kk)*COP+co] = w[t];
}

__global__ void k_prep(const float* __restrict__ emb,
                       const float* __restrict__ ew1, const float* __restrict__ ew2,
                       const float* __restrict__ ew3,
                       const float* __restrict__ er1a, const float* __restrict__ er2a,
                       const float* __restrict__ dr1a, const float* __restrict__ dr2a,
                       const float* __restrict__ dw1, const float* __restrict__ dw2,
                       const float* __restrict__ dw3)
{
  int t = blockIdx.x*256 + threadIdx.x;
  if (t < 1024){
    const float4* e = reinterpret_cast<const float4*>(emb + (size_t)t*64);
    float s = 0.f;
    #pragma unroll
    for (int i=0;i<16;i++){
      float4 v = e[i];
      s = fmaf(v.x,v.x,fmaf(v.y,v.y,fmaf(v.z,v.z,fmaf(v.w,v.w,s))));
    }
    g_ESQ[t] = s; return;
  } t -= 1024;
  if (t < 3072){ trA_i(ew1, g_TW_E1, 3,64,16, t); return; } t -= 3072;
  if (t < 131072){ trA_i(ew2, g_TW_E2, 64,128,16, t); return; } t -= 131072;
  if (t < 147456){ trA_i(ew3, g_TW_E3, 128,128,9, t); return; } t -= 147456;
  if (t < 36864){ trA_i(er1a, g_TW_R1A, 128,32,9, t); return; } t -= 36864;
  if (t < 36864){ trA_i(er2a, g_TW_R2A, 128,32,9, t); return; } t -= 36864;
  if (t < 36864){ trA_i(dr1a, g_TW_DR1A, 128,32,9, t); return; } t -= 36864;
  if (t < 36864){ trA_i(dr2a, g_TW_DR2A, 128,32,9, t); return; } t -= 36864;
  if (t < 73728){
    int ci = t/(128*9); int r = t%(128*9); int co = r/9, kk = r%9;
    int ky = kk/3, kx = kk%3;
    g_TW_DEC[((size_t)ci*9 + (2-ky)*3 + (2-kx))*128 + co] = dw1[t]; return;
  } t -= 73728;
  if (t < 131072){ trB_i(dw2, g_TW_D2, 128,64,16,64, t); return; } t -= 131072;
  if (t < 3072){ trB_i(dw3, g_TW_D3, 64,3,16,4, t); }
}

// ---------------- 3x3 s1 p1 conv at 32x32, f32x2, 2-ci stages ----------------
template<int CIN,int COUT,int COT,bool RIN,bool ROUT,bool HASB>
__global__ void __launch_bounds__(256,3)
k_conv3s(int in_id, int w_id, const float* __restrict__ bias, int out_id)
{
  constexpr int CP   = COT/2;
  constexpr int WSZ  = 9*COT;        // weight floats per plane
  constexpr int WTOT = 2*WSZ;
  static_assert(WTOT <= 256, "weight staging assumes one element per thread");
  static_assert(CIN % 2 == 0, "paired ci staging");
  __shared__ __align__(16) float sIn[2][2][34*40];
  __shared__ __align__(16) float sW [2][WTOT];
  const float* in = gbuf_c(in_id, nullptr);
  const float* W  = gbuf_c(w_id, nullptr);
  float* out = gbuf(out_id);
  int co0 = blockIdx.x*COT;
  int b   = blockIdx.y;
  int tid = threadIdx.x;
  int tx = tid & 7, ty = tid >> 3;
  int x0 = tx*4;

  for (int i=tid; i<34*40; i+=256){
    sIn[0][0][i]=0.f; sIn[0][1][i]=0.f; sIn[1][0][i]=0.f; sIn[1][1][i]=0.f;
  }
  __syncthreads();

  u64 acc[CP][4];
  #pragma unroll
  for (int j=0;j<CP;j++){
    u64 bp = HASB ? pk2(__ldg(bias+co0+2*j), __ldg(bias+co0+2*j+1)) : 0ull;
    #pragma unroll
    for (int p=0;p<4;p++) acc[j][p] = bp;
  }

  const float* ipb = in + (size_t)b*CIN*1024;
  // weight staging: element tid covers plane=tid/WSZ, tap=(tid%WSZ)/COT, co=(tid%WSZ)%COT
  bool wact = tid < WTOT;
  int wpl = tid / WSZ, wrem = tid % WSZ;
  int wtap = wrem / COT, wco = wrem % COT;
  const float* wbase = W + ((size_t)wpl*9 + wtap)*COUT + co0 + wco;

  float4 va = __ldg(reinterpret_cast<const float4*>(ipb) + tid);
  float4 vc = __ldg(reinterpret_cast<const float4*>(ipb + 1024) + tid);
  if (RIN){
    va.x=fmaxf(va.x,0.f); va.y=fmaxf(va.y,0.f); va.z=fmaxf(va.z,0.f); va.w=fmaxf(va.w,0.f);
    vc.x=fmaxf(vc.x,0.f); vc.y=fmaxf(vc.y,0.f); vc.z=fmaxf(vc.z,0.f); vc.w=fmaxf(vc.w,0.f);
  }
  float wv0 = wact ? __ldg(wbase) : 0.f;

  int pb = 0;
  for (int ci=0; ci<CIN; ci+=2){
    float* sp0 = &sIn[pb][0][(ty+1)*40 + 1 + x0];
    sp0[0]=va.x; sp0[1]=va.y; sp0[2]=va.z; sp0[3]=va.w;
    float* sp1 = &sIn[pb][1][(ty+1)*40 + 1 + x0];
    sp1[0]=vc.x; sp1[1]=vc.y; sp1[2]=vc.z; sp1[3]=vc.w;
    if (wact) sW[pb][tid] = wv0;
    __syncthreads();
    if (ci+2 < CIN){
      va = __ldg(reinterpret_cast<const float4*>(ipb + (size_t)(ci+2)*1024) + tid);
      vc = __ldg(reinterpret_cast<const float4*>(ipb + (size_t)(ci+3)*1024) + tid);
      if (RIN){
        va.x=fmaxf(va.x,0.f); va.y=fmaxf(va.y,0.f); va.z=fmaxf(va.z,0.f); va.w=fmaxf(va.w,0.f);
        vc.x=fmaxf(vc.x,0.f); vc.y=fmaxf(vc.y,0.f); vc.z=fmaxf(vc.z,0.f); vc.w=fmaxf(vc.w,0.f);
      }
      if (wact) wv0 = __ldg(wbase + (size_t)(ci+2)*9*COUT);
    }
    #pragma unroll
    for (int pl=0; pl<2; pl++){
      #pragma unroll
      for (int ky=0;ky<3;ky++){
        const float* row = &sIn[pb][pl][(ty+ky)*40 + x0];
        float4 a = *reinterpret_cast<const float4*>(row);
        float e4 = row[4], e5 = row[5];
        u64 vb[6];
        vb[0]=pk2(a.x,a.x); vb[1]=pk2(a.y,a.y); vb[2]=pk2(a.z,a.z);
        vb[3]=pk2(a.w,a.w); vb[4]=pk2(e4,e4);  vb[5]=pk2(e5,e5);
        #pragma unroll
        for (int kx=0;kx<3;kx++){
          const ulonglong2* wq = reinterpret_cast<const ulonglong2*>(&sW[pb][pl*WSZ + (ky*3+kx)*COT]);
          #pragma unroll
          for (int j2=0;j2<CP/2;j2++){
            ulonglong2 wv = wq[j2];
            #pragma unroll
            for (int p=0;p<4;p++){
              fma2(acc[2*j2  ][p], wv.x, vb[kx+p]);
              fma2(acc[2*j2+1][p], wv.y, vb[kx+p]);
            }
          }
        }
      }
    }
    pb ^= 1;
  }
  #pragma unroll
  for (int j=0;j<CP;j++){
    float2 f0=up2(acc[j][0]), f1=up2(acc[j][1]), f2=up2(acc[j][2]), f3=up2(acc[j][3]);
    float4 oe = make_float4(f0.x,f1.x,f2.x,f3.x);
    float4 oo = make_float4(f0.y,f1.y,f2.y,f3.y);
    if (ROUT){
      oe.x=fmaxf(oe.x,0.f); oe.y=fmaxf(oe.y,0.f); oe.z=fmaxf(oe.z,0.f); oe.w=fmaxf(oe.w,0.f);
      oo.x=fmaxf(oo.x,0.f); oo.y=fmaxf(oo.y,0.f); oo.z=fmaxf(oo.z,0.f); oo.w=fmaxf(oo.w,0.f);
    }
    *reinterpret_cast<float4*>(out + ((size_t)(b*COUT+co0+2*j  )*32 + ty)*32 + x0) = oe;
    *reinterpret_cast<float4*>(out + ((size_t)(b*COUT+co0+2*j+1)*32 + ty)*32 + x0) = oo;
  }
}

// ---------------- 4x4 s2 p1 conv, f32x2, dbl-buf input+weights ---------------
template<int CIN,int COUT,int HIN,int COT>
__global__ void __launch_bounds__(256,2)
k_conv4s(const float* __restrict__ ext_in, int in_id, int w_id,
         const float* __restrict__ bias, int out_id)
{
  constexpr int CP = COT/2;
  constexpr int HOUT = HIN/2;
  constexpr int XT   = HOUT/32;
  constexpr int WSZ  = 16*COT;
  __shared__ __align__(16) float sIn[2][66*72];
  __shared__ __align__(16) float sW [2][WSZ];
  const float* in = gbuf_c(in_id, ext_in);
  const float* W  = gbuf_c(w_id, nullptr);
  float* out = gbuf(out_id);
  int co0 = blockIdx.x*COT;
  int oy0 = (blockIdx.y/XT)*32, ox0 = (blockIdx.y%XT)*32;
  int b = blockIdx.z;
  int tid = threadIdx.x;
  int tx = tid & 7, ty = tid >> 3;
  int x0 = tx*4;

  u64 acc[CP][4];
  #pragma unroll
  for (int j=0;j<CP;j++){
    u64 bp = pk2(__ldg(bias+co0+2*j), __ldg(bias+co0+2*j+1));
    #pragma unroll
    for (int p=0;p<4;p++) acc[j][p] = bp;
  }

  int iy0 = oy0*2 - 1, ix0 = ox0*2 - 1;
  int wk = tid / COT, wj = tid % COT;
  bool wact = tid < WSZ;
  const float* wsrc0 = W + (size_t)wk*COUT + co0 + wj;

  float sreg[18];
  {
    const float* ip = in + (size_t)b*CIN*HIN*HIN;
    #pragma unroll
    for (int t=0;t<18;t++){
      int s = tid + t*256; float v = 0.f;
      if (s < 4356){
        int r = s/66, c = s - r*66;
        int giy = iy0 + r, gix = ix0 + c;
        if (giy>=0 && giy<HIN && gix>=0 && gix<HIN) v = __ldg(ip + (size_t)giy*HIN + gix);
      }
      sreg[t] = v;
    }
  }
  float wv0 = wact ? __ldg(wsrc0) : 0.f;

  int pb = 0;
  for (int ci=0; ci<CIN; ci++){
    #pragma unroll
    for (int t=0;t<18;t++){
      int s = tid + t*256;
      if (s < 4356){ int r = s/66, c = s - r*66; sIn[pb][r*72 + c] = sreg[t]; }
    }
    if (wact) sW[pb][tid] = wv0;
    __syncthreads();
    if (ci+1 < CIN){
      const float* ip = in + (size_t)(b*CIN+ci+1)*HIN*HIN;
      #pragma unroll
      for (int t=0;t<18;t++){
        int s = tid + t*256; float v = 0.f;
        if (s < 4356){
          int r = s/66, c = s - r*66;
          int giy = iy0 + r, gix = ix0 + c;
          if (giy>=0 && giy<HIN && gix>=0 && gix<HIN) v = __ldg(ip + (size_t)giy*HIN + gix);
        }
        sreg[t] = v;
      }
      if (wact) wv0 = __ldg(wsrc0 + (size_t)(ci+1)*16*COUT);
    }
    #pragma unroll
    for (int ky=0;ky<4;ky++){
      const float* row = &sIn[pb][(2*ty+ky)*72 + 2*x0];
      float4 a  = *reinterpret_cast<const float4*>(row);
      float4 bq = *reinterpret_cast<const float4*>(row+4);
      float e8 = row[8], e9 = row[9];
      u64 vb[10];
      vb[0]=pk2(a.x,a.x); vb[1]=pk2(a.y,a.y); vb[2]=pk2(a.z,a.z); vb[3]=pk2(a.w,a.w);
      vb[4]=pk2(bq.x,bq.x); vb[5]=pk2(bq.y,bq.y); vb[6]=pk2(bq.z,bq.z); vb[7]=pk2(bq.w,bq.w);
      vb[8]=pk2(e8,e8); vb[9]=pk2(e9,e9);
      #pragma unroll
      for (int kx=0;kx<4;kx++){
        const ulonglong2* wq = reinterpret_cast<const ulonglong2*>(&sW[pb][(ky*4+kx)*COT]);
        #pragma unroll
        for (int j2=0;j2<CP/2;j2++){
          ulonglong2 wv = wq[j2];
          #pragma unroll
          for (int p=0;p<4;p++){
            fma2(acc[2*j2  ][p], wv.x, vb[kx+2*p]);
            fma2(acc[2*j2+1][p], wv.y, vb[kx+2*p]);
          }
        }
      }
    }
    pb ^= 1;
  }
  #pragma unroll
  for (int j=0;j<CP;j++){
    float2 f0=up2(acc[j][0]), f1=up2(acc[j][1]), f2=up2(acc[j][2]), f3=up2(acc[j][3]);
    float4 oe = make_float4(fmaxf(f0.x,0.f),fmaxf(f1.x,0.f),fmaxf(f2.x,0.f),fmaxf(f3.x,0.f));
    float4 oo = make_float4(fmaxf(f0.y,0.f),fmaxf(f1.y,0.f),fmaxf(f2.y,0.f),fmaxf(f3.y,0.f));
    *reinterpret_cast<float4*>(out + ((size_t)(b*COUT+co0+2*j  )*HOUT + oy0+ty)*HOUT + ox0+x0) = oe;
    *reinterpret_cast<float4*>(out + ((size_t)(b*COUT+co0+2*j+1)*HOUT + oy0+ty)*HOUT + ox0+x0) = oo;
  }
}

// ---------------- 1x1 conv residual-add, smem weights, input read once -------
__global__ void __launch_bounds__(256)
k_res1x1v(int t_id, const float* __restrict__ w, int x_id)
{
  __shared__ float sw[128*32];
  const float* t = gbuf_c(t_id, nullptr);
  float* x = gbuf(x_id);
  int b = blockIdx.y, p = blockIdx.x*256 + threadIdx.x;
  for (int i=threadIdx.x; i<4096; i+=256) sw[i] = __ldg(w+i);
  __syncthreads();
  float rv[32];
  #pragma unroll
  for (int ci=0;ci<32;ci++) rv[ci] = __ldg(t + (size_t)(b*32+ci)*1024 + p);
  #pragma unroll 4
  for (int co=0;co<128;co++){
    float a = 0.f;
    const float* wr = &sw[co*32];
    #pragma unroll
    for (int ci=0;ci<32;ci++) a = fmaf(wr[ci], rv[ci], a);
    x[(size_t)(b*128+co)*1024 + p] += a;
  }
}

// ---------------- pre-quant 1x1: relu(in) -> z NHWC, smem weights ------------
__global__ void __launch_bounds__(256)
k_pqv(int in_id, const float* __restrict__ w, const float* __restrict__ bias)
{
  __shared__ float swT[128*64];
  const float* h = gbuf_c(in_id, nullptr);
  int b = blockIdx.y, p = blockIdx.x*256 + threadIdx.x;
  for (int i=threadIdx.x; i<8192; i+=256){
    int d = i >> 7, ci = i & 127;
    swT[ci*64 + d] = __ldg(w + i);
  }
  __syncthreads();
  float acc[64];
  #pragma unroll
  for (int d=0;d<64;d++) acc[d] = __ldg(bias+d);
  const float* ip = h + (size_t)b*128*1024 + p;
  for (int ci=0;ci<128;ci++){
    float v = fmaxf(__ldg(ip + (size_t)ci*1024), 0.f);
    const float4* wr = reinterpret_cast<const float4*>(&swT[ci*64]);
    #pragma unroll
    for (int q=0;q<16;q++){
      float4 wv = wr[q];
      acc[4*q  ]=fmaf(wv.x,v,acc[4*q  ]); acc[4*q+1]=fmaf(wv.y,v,acc[4*q+1]);
      acc[4*q+2]=fmaf(wv.z,v,acc[4*q+2]); acc[4*q+3]=fmaf(wv.w,v,acc[4*q+3]);
    }
  }
  float4* zp = reinterpret_cast<float4*>(g_Z + (size_t)(b*1024+p)*64);
  #pragma unroll
  for (int q=0;q<16;q++) zp[q] = make_float4(acc[4*q],acc[4*q+1],acc[4*q+2],acc[4*q+3]);
}

// ---------------- VQ: argmin, gather to NCHW, loss partials ------------------
__global__ void k_vq(const float* __restrict__ emb){
  __shared__ __align__(16) float sE[128*64];
  __shared__ float sQ[128];
  __shared__ double sred[128];
  int tid = threadIdx.x;
  int n = blockIdx.x*128 + tid;
  int b = n >> 10, p = n & 1023;
  float zr[64];
  {
    const float4* zp = reinterpret_cast<const float4*>(g_Z + (size_t)n*64);
    float4* zr4 = reinterpret_cast<float4*>(zr);
    #pragma unroll
    for (int i=0;i<16;i++) zr4[i] = zp[i];
  }
  float best = FLT_MAX; int bi = 0;
  for (int c=0;c<8;c++){
    const float4* src = reinterpret_cast<const float4*>(emb) + (size_t)c*2048;
    float4* dst = reinterpret_cast<float4*>(sE);
    #pragma unroll
    for (int r=0;r<16;r++) dst[tid + r*128] = src[tid + r*128];
    sQ[tid] = g_ESQ[c*128+tid];
    __syncthreads();
    for (int kk=0;kk<128;kk++){
      const float4* e = reinterpret_cast<const float4*>(sE + kk*64);
      float d0=0.f,d1=0.f,d2=0.f,d3=0.f;
      #pragma unroll
      for (int i=0;i<16;i++){
        float4 ev = e[i];
        float4 zv = reinterpret_cast<float4*>(zr)[i];
        d0 = fmaf(ev.x,zv.x,d0); d1 = fmaf(ev.y,zv.y,d1);
        d2 = fmaf(ev.z,zv.z,d2); d3 = fmaf(ev.w,zv.w,d3);
      }
      float sc = sQ[kk] - 2.f*((d0+d1)+(d2+d3));
      if (sc < best){ best = sc; bi = c*128+kk; }   // strict < : first min
    }
    __syncthreads();
  }
  g_IDX[n] = bi;
  const float* er = emb + (size_t)bi*64;
  float ls = 0.f;
  #pragma unroll
  for (int d=0; d<64; d++){
    float e = __ldg(er+d);
    g_ZQ[(size_t)(b*64+d)*1024 + p] = e;
    float df = e - zr[d];
    ls = fmaf(df,df,ls);
  }
  sred[tid] = (double)ls;
  __syncthreads();
  #pragma unroll
  for (int s=64;s>0;s>>=1){
    if (tid<s) sred[tid] += sred[tid+s];
    __syncthreads();
  }
  if (tid==0) g_PART[blockIdx.x] = sred[0];
}

// ---------------- ConvTranspose 4x4 s2 p1: 128@32 -> 64@64, 2-ci stages ------
__global__ void __launch_bounds__(256,2)
k_convT2s(const float* __restrict__ bias)
{
  constexpr int CP = 8;  // 16 couts as 8 pairs
  __shared__ __align__(16) float sIn[2][2][400];
  __shared__ __align__(16) float sW [2][512];
  int co0 = blockIdx.x*16;
  int yq0 = blockIdx.y*8;
  int b   = blockIdx.z;
  int tid = threadIdx.x;
  int tx = tid & 31, ty = tid >> 5;

  u64 acc[CP][4];
  #pragma unroll
  for (int j=0;j<CP;j++)
    #pragma unroll
    for (int q=0;q<4;q++) acc[j][q] = 0ull;

  const float* ipb = g_D1 + (size_t)b*128*1024;
  int r0 = tid/34, c0 = tid - r0*34;
  int r1 = (tid+256)/34, c1 = (tid+256) - r1*34;
  bool has1 = (tid+256) < 340;
  int giy0 = yq0-1+r0, gix0 = c0-1;
  int giy1 = yq0-1+r1, gix1 = c1-1;
  bool in0 = (giy0>=0 && giy0<32 && gix0>=0 && gix0<32);
  bool in1 = has1 && (giy1>=0 && giy1<32 && gix1>=0 && gix1<32);
  int off0 = giy0*32+gix0, off1 = giy1*32+gix1;
  // weights: thread -> (tap=tid>>4, co=tid&15); plane0 at sW[tid], plane1 at sW[256+tid]
  const float* wsrc = g_TW_D2 + (size_t)(tid>>4)*64 + co0 + (tid&15);

  float a0,a1,b0v,b1v;
  a0  = in0 ? fmaxf(__ldg(ipb + off0),0.f) : 0.f;
  a1  = in1 ? fmaxf(__ldg(ipb + off1),0.f) : 0.f;
  b0v = in0 ? fmaxf(__ldg(ipb + 1024 + off0),0.f) : 0.f;
  b1v = in1 ? fmaxf(__ldg(ipb + 1024 + off1),0.f) : 0.f;
  float wa = __ldg(wsrc);
  float wb = __ldg(wsrc + 1024);

  int pb = 0;
  for (int ci=0; ci<128; ci+=2){
    sIn[pb][0][r0*40 + c0] = a0;
    if (has1) sIn[pb][0][r1*40 + c1] = a1;
    sIn[pb][1][r0*40 + c0] = b0v;
    if (has1) sIn[pb][1][r1*40 + c1] = b1v;
    sW[pb][tid] = wa;
    sW[pb][256+tid] = wb;
    __syncthreads();
    if (ci+2 < 128){
      const float* ip0 = ipb + (size_t)(ci+2)*1024;
      const float* ip1 = ipb + (size_t)(ci+3)*1024;
      a0  = in0 ? fmaxf(__ldg(ip0 + off0),0.f) : 0.f;
      a1  = in1 ? fmaxf(__ldg(ip0 + off1),0.f) : 0.f;
      b0v = in0 ? fmaxf(__ldg(ip1 + off0),0.f) : 0.f;
      b1v = in1 ? fmaxf(__ldg(ip1 + off1),0.f) : 0.f;
      wa = __ldg(wsrc + (size_t)(ci+2)*1024);
      wb = __ldg(wsrc + (size_t)(ci+3)*1024);
    }
    #pragma unroll
    for (int pl=0; pl<2; pl++){
      u64 rp[9];
      #pragma unroll
      for (int dy=0;dy<3;dy++)
        #pragma unroll
        for (int dx=0;dx<3;dx++){
          float rv = sIn[pb][pl][(ty+dy)*40 + tx+dx];
          rp[dy*3+dx] = pk2(rv,rv);
        }
      #pragma unroll
      for (int ky=0;ky<4;ky++){
        #pragma unroll
        for (int kx=0;kx<4;kx++){
          u64 rv = rp[((4-ky)>>1)*3 + ((4-kx)>>1)];
          const int pp = (((ky&1)^1)<<1) | ((kx&1)^1);
          const ulonglong2* wq = reinterpret_cast<const ulonglong2*>(&sW[pb][pl*256 + (ky*4+kx)*16]);
          #pragma unroll
          for (int j2=0;j2<CP/2;j2++){
            ulonglong2 wv = wq[j2];
            fma2(acc[2*j2  ][pp], wv.x, rv);
            fma2(acc[2*j2+1][pp], wv.y, rv);
          }
        }
      }
    }
    pb ^= 1;
  }
  int yq = yq0 + ty;
  #pragma unroll
  for (int j=0;j<CP;j++){
    float2 f0=up2(acc[j][0]), f1=up2(acc[j][1]), f2=up2(acc[j][2]), f3=up2(acc[j][3]);
    float bvx = __ldg(bias+co0+2*j), bvy = __ldg(bias+co0+2*j+1);
    float* opx = g_U1 + (size_t)(b*64+co0+2*j)*4096;
    float* opy = g_U1 + (size_t)(b*64+co0+2*j+1)*4096;
    float2 ex0 = make_float2(fmaxf(f0.x+bvx,0.f), fmaxf(f1.x+bvx,0.f));
    float2 ex1 = make_float2(fmaxf(f2.x+bvx,0.f), fmaxf(f3.x+bvx,0.f));
    float2 ey0 = make_float2(fmaxf(f0.y+bvy,0.f), fmaxf(f1.y+bvy,0.f));
    float2 ey1 = make_float2(fmaxf(f2.y+bvy,0.f), fmaxf(f3.y+bvy,0.f));
    *reinterpret_cast<float2*>(opx + (2*yq+0)*64 + 2*tx) = ex0;
    *reinterpret_cast<float2*>(opx + (2*yq+1)*64 + 2*tx) = ex1;
    *reinterpret_cast<float2*>(opy + (2*yq+0)*64 + 2*tx) = ey0;
    *reinterpret_cast<float2*>(opy + (2*yq+1)*64 + 2*tx) = ey1;
  }
}

// ---------------- ConvTranspose 4x4 s2 p1: 64@64 -> 3@128 (recon) ------------
__global__ void __launch_bounds__(256,2)
k_convT3s(const float* __restrict__ bias, float* __restrict__ out)
{
  __shared__ __align__(16) float sIn[2][10*40];
  __shared__ __align__(16) float sW [2][64];
  int xq0 = blockIdx.x*32;
  int yq0 = blockIdx.y*8;
  int b   = blockIdx.z;
  int tid = threadIdx.x;
  int tx = tid & 31, ty = tid >> 5;

  float acc[3][4];
  #pragma unroll
  for (int j=0;j<3;j++)
    #pragma unroll
    for (int q=0;q<4;q++) acc[j][q]=0.f;

  const float* ipb = g_U1 + (size_t)b*64*4096;
  int r0 = tid/34, c0 = tid - r0*34;
  int r1 = (tid+256)/34, c1 = (tid+256) - r1*34;
  bool has1 = (tid+256) < 340;
  bool wact = tid < 64;
  float s0, s1 = 0.f;
  {
    int giy = yq0-1+r0, gix = xq0-1+c0;
    s0 = (giy>=0&&giy<64&&gix>=0&&gix<64)?__ldg(ipb+giy*64+gix):0.f;
    if (has1){
      int giy1 = yq0-1+r1, gix1 = xq0-1+c1;
      s1 = (giy1>=0&&giy1<64&&gix1>=0&&gix1<64)?__ldg(ipb+giy1*64+gix1):0.f;
    }
  }
  float wv0 = wact ? __ldg(g_TW_D3 + tid) : 0.f;
  int pb = 0;
  for (int ci=0; ci<64; ci++){
    sIn[pb][r0*40 + c0] = s0;
    if (has1) sIn[pb][r1*40 + c1] = s1;
    if (wact) sW[pb][tid] = wv0;
    __syncthreads();
    if (ci+1 < 64){
      const float* ip = ipb + (size_t)(ci+1)*4096;
      int giy = yq0-1+r0, gix = xq0-1+c0;
      s0 = (giy>=0&&giy<64&&gix>=0&&gix<64)?__ldg(ip+giy*64+gix):0.f;
      if (has1){
        int giy1 = yq0-1+r1, gix1 = xq0-1+c1;
        s1 = (giy1>=0&&giy1<64&&gix1>=0&&gix1<64)?__ldg(ip+giy1*64+gix1):0.f;
      }
      if (wact) wv0 = __ldg(g_TW_D3 + (size_t)(ci+1)*64 + tid);
    }
    float r3[3][3];
    #pragma unroll
    for (int dy=0;dy<3;dy++)
      #pragma unroll
      for (int dx=0;dx<3;dx++)
        r3[dy][dx] = sIn[pb][(ty+dy)*40 + tx+dx];
    #pragma unroll
    for (int ky=0;ky<4;ky++){
      #pragma unroll
      for (int kx=0;kx<4;kx++){
        float rv = r3[(4-ky)>>1][(4-kx)>>1];
        const int pp = (((ky&1)^1)<<1) | ((kx&1)^1);
        float4 wv = *reinterpret_cast<const float4*>(&sW[pb][(ky*4+kx)*4]);
        acc[0][pp]=fmaf(wv.x,rv,acc[0][pp]);
        acc[1][pp]=fmaf(wv.y,rv,acc[1][pp]);
        acc[2][pp]=fmaf(wv.z,rv,acc[2][pp]);
      }
    }
    pb ^= 1;
  }
  int yq = yq0 + ty, xq = xq0 + tx;
  #pragma unroll
  for (int j=0;j<3;j++){
    float bv = __ldg(bias+j);
    float* op = out + (size_t)(b*3+j)*16384;
    float2 e0 = make_float2(acc[j][0]+bv, acc[j][1]+bv);
    float2 e1 = make_float2(acc[j][2]+bv, acc[j][3]+bv);
    *reinterpret_cast<float2*>(op + (2*yq+0)*128 + 2*xq) = e0;
    *reinterpret_cast<float2*>(op + (2*yq+1)*128 + 2*xq) = e1;
  }
}

// ---------------- finalize: idx as float + deterministic loss ----------------
__global__ void k_final(float* __restrict__ out){
  int t = blockIdx.x*blockDim.x + threadIdx.x;
  if (t < 65536) out[3145730 + t] = (float)g_IDX[t];
  if (t == 0){
    double s = 0.0;
    for (int i=0;i<512;i++) s += g_PART[i];
    float m = (float)(s / 4194304.0);
    out[3145728] = m;   // codebook_loss
    out[3145729] = m;   // commitment_loss (identical value)
  }
}

// ---------------- launcher ---------------------------------------------------
extern "C" void kernel_launch(void* const* d_in, const int* in_sizes, int n_in,
                              void* d_out, int out_size)
{
  const float* patch=(const float*)d_in[0];
  const float* ew1=(const float*)d_in[1];  const float* eb1=(const float*)d_in[2];
  const float* ew2=(const float*)d_in[3];  const float* eb2=(const float*)d_in[4];
  const float* ew3=(const float*)d_in[5];  const float* eb3=(const float*)d_in[6];
  const float* er1a=(const float*)d_in[7]; const float* er1b=(const float*)d_in[8];
  const float* er2a=(const float*)d_in[9]; const float* er2b=(const float*)d_in[10];
  const float* pqw=(const float*)d_in[11]; const float* pqb=(const float*)d_in[12];
  const float* emb=(const float*)d_in[13];
  const float* dw1=(const float*)d_in[14]; const float* db1=(const float*)d_in[15];
  const float* dr1a=(const float*)d_in[16];const float* dr1b=(const float*)d_in[17];
  const float* dr2a=(const float*)d_in[18];const float* dr2b=(const float*)d_in[19];
  const float* dw2=(const float*)d_in[20]; const float* db2=(const float*)d_in[21];
  const float* dw3=(const float*)d_in[22]; const float* db3=(const float*)d_in[23];
  float* out = (float*)d_out;
  (void)in_sizes; (void)n_in; (void)out_size;

  // esq + all weight transposes in one kernel
  k_prep<<<2492,256>>>(emb, ew1, ew2, ew3, er1a, er2a, dr1a, dr2a, dw1, dw2, dw3);

  // encoder
  k_conv4s<3,64,128,16> <<<dim3(4,4,NB),256>>>(patch, -1, 10, eb1, 0);
  k_conv4s<64,128,64,8> <<<dim3(16,1,NB),256>>>(nullptr, 0, 11, eb2, 1);
  k_conv3s<128,128,8,false,false,true><<<dim3(16,NB),256>>>(1, 12, eb3, 2);
  // residual block 1
  k_conv3s<128,32,8,true,true,false><<<dim3(4,NB),256>>>(2, 13, nullptr, 3);
  k_res1x1v<<<dim3(4,NB),256>>>(3, er1b, 2);
  // residual block 2
  k_conv3s<128,32,8,true,true,false><<<dim3(4,NB),256>>>(2, 14, nullptr, 3);
  k_res1x1v<<<dim3(4,NB),256>>>(3, er2b, 2);
  // pre-quant (relu fused into input)
  k_pqv<<<dim3(4,NB),256>>>(2, pqw, pqb);
  // vector quantization
  k_vq<<<512,128>>>(emb);

  // decoder
  k_conv3s<64,128,8,false,false,true><<<dim3(16,NB),256>>>(5, 17, db1, 6);
  k_conv3s<128,32,8,true,true,false><<<dim3(4,NB),256>>>(6, 15, nullptr, 3);
  k_res1x1v<<<dim3(4,NB),256>>>(3, dr1b, 6);
  k_conv3s<128,32,8,true,true,false><<<dim3(4,NB),256>>>(6, 16, nullptr, 3);
  k_res1x1v<<<dim3(4,NB),256>>>(3, dr2b, 6);
  k_convT2s<<<dim3(4,4,NB),256>>>(db2);
  k_convT3s<<<dim3(2,8,NB),256>>>(db3, out);

  // losses + indices
  k_final<<<256,256>>>(out);
}